// round 12
// baseline (speedup 1.0000x reference)
#include <cuda_runtime.h>
#include <cuda_bf16.h>
#include <cstdint>

#define HH 256
#define WW 256
#define CC 128
#define HWSZ 65536
#define IMG (CC * HH * WW)          // 8388608 floats per frame
#define VIMG (36ull * 128 * 4096)   // transformed plane per image (elems)

// ---------------- scratch (__device__ globals; no allocations) -------------
__device__ float g_Q[2ull * IMG];
__device__ float g_KV[4ull * IMG];
__device__ float g_KVw[8ull * IMG];
__device__ float g_V[14ull * VIMG];      // reused as 2 bf16 planes (hi, lo)
__device__ float g_M[14ull * VIMG];
__device__ float g_U[3ull * 36 * 128 * 128];  // reused as 2 bf16 planes

// ---------------- packed f32x2 helpers --------------------------------------
__device__ __forceinline__ unsigned long long pack2(float x, float y) {
    unsigned long long r;
    asm("mov.b64 %0, {%1,%2};" : "=l"(r) : "f"(x), "f"(y));
    return r;
}
__device__ __forceinline__ void unpack2(unsigned long long v, float& x, float& y) {
    asm("mov.b64 {%0,%1}, %2;" : "=f"(x), "=f"(y) : "l"(v));
}
__device__ __forceinline__ void ffma2(unsigned long long& d,
                                      unsigned long long a,
                                      unsigned long long b) {
    asm("fma.rn.f32x2 %0, %1, %2, %0;" : "+l"(d) : "l"(a), "l"(b));
}

// ---------------- cp.async / ldmatrix / mma helpers -------------------------
__device__ __forceinline__ void cp16(uint32_t saddr, const void* g) {
    asm volatile("cp.async.cg.shared.global [%0], [%1], 16;"
                 :: "r"(saddr), "l"(g) : "memory");
}
#define CP_COMMIT() asm volatile("cp.async.commit_group;" ::: "memory")
#define CP_WAIT(n)  asm volatile("cp.async.wait_group %0;" :: "n"(n) : "memory")

__device__ __forceinline__ uint32_t smem_u32(const void* p) {
    uint32_t a;
    asm("{ .reg .u64 t; cvta.to.shared.u64 t, %1; cvt.u32.u64 %0, t; }"
        : "=r"(a) : "l"(p));
    return a;
}
__device__ __forceinline__ void ldsm4(uint32_t* r, uint32_t a) {
    asm volatile("ldmatrix.sync.aligned.m8n8.x4.shared.b16 {%0,%1,%2,%3}, [%4];"
        : "=r"(r[0]), "=r"(r[1]), "=r"(r[2]), "=r"(r[3]) : "r"(a));
}
__device__ __forceinline__ void ldsm4t(uint32_t* r, uint32_t a) {
    asm volatile("ldmatrix.sync.aligned.m8n8.x4.trans.shared.b16 {%0,%1,%2,%3}, [%4];"
        : "=r"(r[0]), "=r"(r[1]), "=r"(r[2]), "=r"(r[3]) : "r"(a));
}
__device__ __forceinline__ void mma_bf16(float* d, const uint32_t* a,
                                         uint32_t b0, uint32_t b1) {
    asm volatile(
        "mma.sync.aligned.m16n8k16.row.col.f32.bf16.bf16.f32 "
        "{%0,%1,%2,%3}, {%4,%5,%6,%7}, {%8,%9}, {%0,%1,%2,%3};"
        : "+f"(d[0]), "+f"(d[1]), "+f"(d[2]), "+f"(d[3])
        : "r"(a[0]), "r"(a[1]), "r"(a[2]), "r"(a[3]), "r"(b0), "r"(b1));
}

// ---------------- Winograd F(4x4,3x3) transform primitives ------------------
#define BTCOMB(d0,d1,d2,d3,d4,d5,o0,o1,o2,o3,o4,o5) do {                   \
    o0 = 4.f*(d0) - 5.f*(d2) + (d4);                                       \
    float _a = (d4) - 4.f*(d2), _b = (d3) - 4.f*(d1);                      \
    o1 = _a + _b; o2 = _a - _b;                                            \
    float _c = (d4) - (d2), _e = 2.f*((d3) - (d1));                        \
    o3 = _c + _e; o4 = _c - _e;                                            \
    o5 = 4.f*(d1) - 5.f*(d3) + (d5);                                       \
} while (0)

#define ATCOMB(m0,m1,m2,m3,m4,m5,o0,o1,o2,o3) do {                         \
    float _s = (m1)+(m2), _d = (m1)-(m2), _t = (m3)+(m4), _u = (m3)-(m4);  \
    o0 = (m0) + _s + _t;                                                   \
    o1 = _d + 2.f*_u;                                                      \
    o2 = _s + 4.f*_t;                                                      \
    o3 = _d + 8.f*_u + (m5);                                               \
} while (0)

#define GCOMB(w0,w1,w2,o0,o1,o2,o3,o4,o5) do {                             \
    o0 = 0.25f*(w0);                                                       \
    float _n = -(w0) - (w2);                                               \
    o1 = (_n - (w1)) * (1.f/6.f);                                          \
    o2 = (_n + (w1)) * (1.f/6.f);                                          \
    float _p = (w0)*(1.f/24.f) + (w2)*(1.f/6.f), _q = (w1)*(1.f/12.f);     \
    o3 = _p + _q; o4 = _p - _q;                                            \
    o5 = (w2);                                                             \
} while (0)

__device__ __forceinline__ void bf16_split(float v, __nv_bfloat16& h,
                                           __nv_bfloat16& l) {
    h = __float2bfloat16(v);
    l = __float2bfloat16(v - __bfloat162float(h));
}

// ---------------------------------------------------------------------------
// Filter transform -> bf16 hi/lo planes, layout [set][pos][oc][ic]
// ---------------------------------------------------------------------------
__global__ __launch_bounds__(256) void wino_filt3(
    const float* __restrict__ W0, const float* __restrict__ W1,
    const float* __restrict__ W2, __nv_bfloat16* __restrict__ Uh)
{
    __nv_bfloat16* Ul = Uh + 3ull * 36 * 16384;
    int idx = blockIdx.x * 256 + threadIdx.x;
    if (idx >= 3 * 16384) return;
    int set = idx >> 14, e = idx & 16383;
    int oc = e & 127, ic = e >> 7;
    const float* W = (set == 0) ? W0 : (set == 1) ? W1 : W2;
    size_t soff = (size_t)set * (36 * 16384);
    float w[3][3];
#pragma unroll
    for (int a = 0; a < 3; ++a)
#pragma unroll
        for (int b = 0; b < 3; ++b)
            w[a][b] = W[(size_t)oc * 1152 + ic * 9 + a * 3 + b];
    float ee[6][3];
#pragma unroll
    for (int b = 0; b < 3; ++b)
        GCOMB(w[0][b], w[1][b], w[2][b],
              ee[0][b], ee[1][b], ee[2][b], ee[3][b], ee[4][b], ee[5][b]);
#pragma unroll
    for (int i = 0; i < 6; ++i) {
        float u[6];
        GCOMB(ee[i][0], ee[i][1], ee[i][2], u[0], u[1], u[2], u[3], u[4], u[5]);
#pragma unroll
        for (int j = 0; j < 6; ++j) {
            size_t off = soff + (size_t)(i * 6 + j) * 16384 + oc * 128 + ic;
            __nv_bfloat16 h, l;
            bf16_split(u[j], h, l);
            Uh[off] = h; Ul[off] = l;
        }
    }
}

// ---------------------------------------------------------------------------
// Merged input transform -> bf16 hi/lo V planes [img][pos][ic][tile]
// ---------------------------------------------------------------------------
__global__ __launch_bounds__(256) void wino_in14(
    const float* __restrict__ xq, const float* __restrict__ xkv,
    const float* __restrict__ xkvw, __nv_bfloat16* __restrict__ vh)
{
    __nv_bfloat16* vl = vh + 14ull * VIMG;
    __shared__ __align__(16) float s_d[4][6][264];
    int img = blockIdx.z, ty = blockIdx.y, c4 = blockIdx.x;
    int tid = threadIdx.x;
    const float* xb;
    if (img < 2)      xb = xq   + (size_t)img * IMG;
    else if (img < 6) xb = xkv  + (size_t)(img - 2) * IMG;
    else              xb = xkvw + (size_t)(img - 6) * IMG;
    xb += (size_t)(c4 * 4) * HWSZ;

    for (int i = tid; i < 4 * 6 * 258; i += 256) {
        int c = i / (6 * 258);
        int rem = i - c * (6 * 258);
        int r = rem / 258, col = rem - r * 258;
        int gy = ty * 4 - 1 + r, gx = col - 1;
        float v = 0.f;
        if ((unsigned)gy < 256u && (unsigned)gx < 256u)
            v = xb[(size_t)c * HWSZ + gy * 256 + gx];
        s_d[c][r][col] = v;
    }
    __syncthreads();

    int tx = tid & 63, c = tid >> 6;
    float d[6][6];
#pragma unroll
    for (int r = 0; r < 6; ++r) {
        const float4* row = (const float4*)s_d[c][r];
        float4 a = row[tx], b = row[tx + 1];
        d[r][0] = a.x; d[r][1] = a.y; d[r][2] = a.z;
        d[r][3] = a.w; d[r][4] = b.x; d[r][5] = b.y;
    }
    float e[6][6];
#pragma unroll
    for (int j = 0; j < 6; ++j)
        BTCOMB(d[0][j], d[1][j], d[2][j], d[3][j], d[4][j], d[5][j],
               e[0][j], e[1][j], e[2][j], e[3][j], e[4][j], e[5][j]);

    size_t base = (size_t)img * VIMG + (size_t)(c4 * 4 + c) * 4096 +
                  ty * 64 + tx;
#pragma unroll
    for (int i = 0; i < 6; ++i) {
        float o[6];
        BTCOMB(e[i][0], e[i][1], e[i][2], e[i][3], e[i][4], e[i][5],
               o[0], o[1], o[2], o[3], o[4], o[5]);
#pragma unroll
        for (int j = 0; j < 6; ++j) {
            size_t off = base + (size_t)(i * 6 + j) * 524288;
            __nv_bfloat16 h, l;
            bf16_split(o[j], h, l);
            vh[off] = h; vl[off] = l;
        }
    }
}

// FF-stage input transform (2 images from gQ)
__global__ __launch_bounds__(256) void wino_in(
    const float* __restrict__ x, __nv_bfloat16* __restrict__ vh)
{
    __nv_bfloat16* vl = vh + 14ull * VIMG;
    __shared__ __align__(16) float s_d[4][6][264];
    int img = blockIdx.z, ty = blockIdx.y, c4 = blockIdx.x;
    int tid = threadIdx.x;
    const float* xb = x + (size_t)img * IMG + (size_t)(c4 * 4) * HWSZ;

    for (int i = tid; i < 4 * 6 * 258; i += 256) {
        int c = i / (6 * 258);
        int rem = i - c * (6 * 258);
        int r = rem / 258, col = rem - r * 258;
        int gy = ty * 4 - 1 + r, gx = col - 1;
        float v = 0.f;
        if ((unsigned)gy < 256u && (unsigned)gx < 256u)
            v = xb[(size_t)c * HWSZ + gy * 256 + gx];
        s_d[c][r][col] = v;
    }
    __syncthreads();

    int tx = tid & 63, c = tid >> 6;
    float d[6][6];
#pragma unroll
    for (int r = 0; r < 6; ++r) {
        const float4* row = (const float4*)s_d[c][r];
        float4 a = row[tx], b = row[tx + 1];
        d[r][0] = a.x; d[r][1] = a.y; d[r][2] = a.z;
        d[r][3] = a.w; d[r][4] = b.x; d[r][5] = b.y;
    }
    float e[6][6];
#pragma unroll
    for (int j = 0; j < 6; ++j)
        BTCOMB(d[0][j], d[1][j], d[2][j], d[3][j], d[4][j], d[5][j],
               e[0][j], e[1][j], e[2][j], e[3][j], e[4][j], e[5][j]);

    size_t base = (size_t)img * VIMG + (size_t)(c4 * 4 + c) * 4096 +
                  ty * 64 + tx;
#pragma unroll
    for (int i = 0; i < 6; ++i) {
        float o[6];
        BTCOMB(e[i][0], e[i][1], e[i][2], e[i][3], e[i][4], e[i][5],
               o[0], o[1], o[2], o[3], o[4], o[5]);
#pragma unroll
        for (int j = 0; j < 6; ++j) {
            size_t off = base + (size_t)(i * 6 + j) * 524288;
            __nv_bfloat16 h, l;
            bf16_split(o[j], h, l);
            vh[off] = h; vl[off] = l;
        }
    }
}

// ---------------------------------------------------------------------------
// Winograd GEMM via mma.sync (HMMA) + bf16 3-term split.  (R11 passing version)
// ---------------------------------------------------------------------------
#define GEMM_SMEM 75776
#define AS_STAGE 20480
#define AS_TERM  10240
#define BS_BASE  40960
#define BS_STAGE 17408
#define BS_TERM  8704

__global__ __launch_bounds__(256, 1) void wino_gemm_mma(
    const __nv_bfloat16* __restrict__ vh, const __nv_bfloat16* __restrict__ uh,
    float* __restrict__ mout, int route)
{
    extern __shared__ __align__(16) char smx[];
    const __nv_bfloat16* vl = vh + 14ull * VIMG;
    const __nv_bfloat16* ul = uh + 3ull * 36 * 16384;

    int pos = blockIdx.y, img = blockIdx.z, tb = blockIdx.x;
    int tid = threadIdx.x, l = tid & 31, wid = tid >> 5;
    int warp_m = wid & 1, warp_n = wid >> 1;

    int uset = route ? ((img < 2) ? 0 : 1) : 2;
    size_t uoff = (size_t)uset * (36 * 16384) + (size_t)pos * 16384;
    size_t voff = (size_t)img * VIMG + (size_t)pos * 524288 + tb * 128;

    uint32_t sb = smem_u32(smx);

#define COPY_CHUNK(chunk, buf) do {                                         \
    int _ic0 = (chunk) * 32;                                                \
    _Pragma("unroll")                                                       \
    for (int _i = 0; _i < 4; ++_i) {                                        \
        int _t = tid + _i * 256;                                            \
        int _term = _t >> 9, _r = (_t >> 2) & 127, _s = _t & 3;             \
        const __nv_bfloat16* _src =                                         \
            (_term ? ul : uh) + uoff + _r * 128 + _ic0 + _s * 8;            \
        cp16(sb + (buf) * AS_STAGE + _term * AS_TERM + _r * 80 + _s * 16,   \
             _src);                                                         \
        int _bt = _t >> 9, _rem = _t & 511, _br = _rem >> 4, _bs = _rem & 15;\
        const __nv_bfloat16* _bsrc =                                        \
            (_bt ? vl : vh) + voff + (size_t)(_ic0 + _br) * 4096 + _bs * 8; \
        cp16(sb + BS_BASE + (buf) * BS_STAGE + _bt * BS_TERM +              \
             _br * 272 + _bs * 16, _bsrc);                                  \
    }                                                                       \
    CP_COMMIT();                                                            \
} while (0)

    float d[4][4][4];
#pragma unroll
    for (int mt = 0; mt < 4; ++mt)
#pragma unroll
        for (int nt = 0; nt < 4; ++nt)
#pragma unroll
            for (int k = 0; k < 4; ++k) d[mt][nt][k] = 0.f;

    COPY_CHUNK(0, 0);

    for (int c = 0; c < 4; ++c) {
        int buf = c & 1;
        if (c < 3) {
            COPY_CHUNK(c + 1, buf ^ 1);
            CP_WAIT(1);
        } else {
            CP_WAIT(0);
        }
        __syncthreads();

#pragma unroll
        for (int ks = 0; ks < 2; ++ks) {
            uint32_t ah[4][4], al[4][4], bh[2][4], bl[2][4];
#pragma unroll
            for (int mt = 0; mt < 4; ++mt) {
                uint32_t aa = sb + buf * AS_STAGE +
                    (warp_m * 64 + mt * 16 + (l & 15)) * 80 +
                    ks * 32 + (l >> 4) * 16;
                ldsm4(ah[mt], aa);
                ldsm4(al[mt], aa + AS_TERM);
            }
#pragma unroll
            for (int n2 = 0; n2 < 2; ++n2) {
                uint32_t ba = sb + BS_BASE + buf * BS_STAGE +
                    (ks * 16 + (l & 7) + ((l >> 3) & 1) * 8) * 272 +
                    (warp_n * 32 + n2 * 16) * 2 + (l >> 4) * 16;
                ldsm4t(bh[n2], ba);
                ldsm4t(bl[n2], ba + BS_TERM);
            }
#pragma unroll
            for (int mt = 0; mt < 4; ++mt)
#pragma unroll
                for (int nt = 0; nt < 4; ++nt)
                    mma_bf16(d[mt][nt], ah[mt],
                             bh[nt >> 1][(nt & 1) * 2], bh[nt >> 1][(nt & 1) * 2 + 1]);
#pragma unroll
            for (int mt = 0; mt < 4; ++mt)
#pragma unroll
                for (int nt = 0; nt < 4; ++nt)
                    mma_bf16(d[mt][nt], al[mt],
                             bh[nt >> 1][(nt & 1) * 2], bh[nt >> 1][(nt & 1) * 2 + 1]);
#pragma unroll
            for (int mt = 0; mt < 4; ++mt)
#pragma unroll
                for (int nt = 0; nt < 4; ++nt)
                    mma_bf16(d[mt][nt], ah[mt],
                             bl[nt >> 1][(nt & 1) * 2], bl[nt >> 1][(nt & 1) * 2 + 1]);
        }
        __syncthreads();
    }

    float* Mo = mout + (size_t)img * VIMG + (size_t)pos * 524288 + tb * 128;
#pragma unroll
    for (int mt = 0; mt < 4; ++mt)
#pragma unroll
        for (int nt = 0; nt < 4; ++nt) {
            int oc0 = warp_m * 64 + mt * 16 + (l >> 2);
            int t0  = warp_n * 32 + nt * 8 + (l & 3) * 2;
            float2 v01 = make_float2(d[mt][nt][0], d[mt][nt][1]);
            float2 v23 = make_float2(d[mt][nt][2], d[mt][nt][3]);
            *(float2*)(Mo + (size_t)oc0 * 4096 + t0) = v01;
            *(float2*)(Mo + (size_t)(oc0 + 8) * 4096 + t0) = v23;
        }
#undef COPY_CHUNK
}

// ---------------------------------------------------------------------------
// Merged output transform + bias + PReLU + residual, per-image routing.
// ---------------------------------------------------------------------------
__global__ __launch_bounds__(256) void wino_out14(
    const float* __restrict__ mout,
    const float* __restrict__ r0, const float* __restrict__ r1,
    const float* __restrict__ r2,
    float* __restrict__ y0, float* __restrict__ y1, float* __restrict__ y2,
    const float* __restrict__ bias0, const float* __restrict__ alpha0,
    const float* __restrict__ bias1, const float* __restrict__ alpha1,
    int route)
{
    __shared__ __align__(16) float s_o[8][4][256];
    int img = blockIdx.z, ty = blockIdx.y, og = blockIdx.x;
    int tid = threadIdx.x;

    const float* resid; float* y; const float* bias; const float* alpha;
    if (!route || img < 2) {
        resid = r0 + (size_t)img * IMG; y = y0 + (size_t)img * IMG;
        bias = bias0; alpha = alpha0;
    } else if (img < 6) {
        resid = r1 + (size_t)(img - 2) * IMG; y = y1 + (size_t)(img - 2) * IMG;
        bias = bias1; alpha = alpha1;
    } else {
        resid = r2 + (size_t)(img - 6) * IMG; y = y2 + (size_t)(img - 6) * IMG;
        bias = bias1; alpha = alpha1;
    }

#pragma unroll
    for (int it = 0; it < 2; ++it) {
        int item = tid + it * 256;
        int tx = item & 63, ol = item >> 6;
        const float* Mp = mout + (size_t)img * VIMG +
                          (size_t)(og * 8 + ol) * 4096 + ty * 64 + tx;
        float m[6][6];
#pragma unroll
        for (int pos = 0; pos < 36; ++pos)
            m[pos / 6][pos % 6] = Mp[(size_t)pos * 524288];
        float e[4][6];
#pragma unroll
        for (int j = 0; j < 6; ++j)
            ATCOMB(m[0][j], m[1][j], m[2][j], m[3][j], m[4][j], m[5][j],
                   e[0][j], e[1][j], e[2][j], e[3][j]);
#pragma unroll
        for (int r = 0; r < 4; ++r) {
            float o0, o1, o2, o3;
            ATCOMB(e[r][0], e[r][1], e[r][2], e[r][3], e[r][4], e[r][5],
                   o0, o1, o2, o3);
            ((float4*)s_o[ol][r])[tx] = make_float4(o0, o1, o2, o3);
        }
    }
    __syncthreads();

    float a = alpha[0];
    for (int i = tid; i < 8192; i += 256) {
        int ol = i >> 10, rem = i & 1023, r = rem >> 8, px = rem & 255;
        int oc = og * 8 + ol;
        int gy = ty * 4 + r;
        size_t addr = (size_t)oc * HWSZ + gy * 256 + px;
        float v = s_o[ol][r][px] + bias[oc];
        v = (v >= 0.f) ? v : a * v;
        y[addr] = resid[addr] + v;
    }
}

// ---------------------------------------------------------------------------
// Windowed dual-branch attention v4: QK via HMMA bf16 3-term, softmax on
// smem rows, PV scalar FFMA2 (pre-dup V).
// smem map (floats): [0,8704) Q bf16 planes / later S+Vdup+O aliases;
//   Q bf16: bytes [0,34816); K bf16: bytes [34816,135168)
//   S fp32 [64][392]: floats [0,25088)   (after QK mainloop)
//   P fp32 [384][66]: floats [25088,50432)
//   Vdup ull [64][129]: floats [0,16512) (after P written)
//   mask: floats [50432,50496)
// ---------------------------------------------------------------------------
#define SST 392
#define PST 66
#define VDST 129
#define OST 66
#define OFF_P 25088
#define OFF_SM 50432
#define ATTN_SMEM 201984
#define NK 384

__global__ __launch_bounds__(256) void win_attn(
    float* __restrict__ Qbuf, const float* __restrict__ KV,
    const float* __restrict__ KVw, const float* __restrict__ em)
{
    extern __shared__ __align__(16) float sm[];
    __nv_bfloat16* qbf = (__nv_bfloat16*)sm;           // rows 272B, planes 17408B
    __nv_bfloat16* kbf = (__nv_bfloat16*)sm + 17408;   // rows 784B, planes 50176B
    float* s_s = sm;                                   // [64][392]
    float* s_p = sm + OFF_P;                           // [384][66]
    unsigned long long* s_v2 = (unsigned long long*)sm;// [64][129]
    float* s_m = sm + OFF_SM;

    int bwin = blockIdx.x;
    int bb  = bwin >> 10;
    int wy8 = ((bwin >> 5) & 31) << 3;
    int wx8 = (bwin & 31) << 3;
    int tid = threadIdx.x;
    int l = tid & 31, wid = tid >> 5;
    int warp_m = wid & 1, warp_n = wid >> 1;
    uint32_t sb = smem_u32(sm);

    float* qimg = Qbuf + (size_t)bb * IMG;
    const float* kv0 = KV + (size_t)bb * 2 * IMG;
    const float* kv1 = KVw + (size_t)bb * 4 * IMG;

    // ---- load Q as bf16 hi/lo [q row][c col] (A-layout, 272B rows)
    for (int i = tid; i < 64 * CC; i += 256) {
        int q = i & 63, c = i >> 6;
        int gy = wy8 + (q >> 3), gx = wx8 + (q & 7);
        float v = qimg[(size_t)c * HWSZ + gy * WW + gx];
        __nv_bfloat16 h, lo;
        bf16_split(v, h, lo);
        qbf[q * 136 + c] = h;
        qbf[8704 + q * 136 + c] = lo;
    }
    if (tid < 64) {
        int gy = wy8 + (tid >> 3), gx = wx8 + (tid & 7);
        s_m[tid] = em[(size_t)bb * HWSZ + gy * WW + gx];
    }

    // ================= QK via HMMA: S[64q x 384k], k=c dims in 2 chunks =====
    float d[2][12][4];
#pragma unroll
    for (int mt = 0; mt < 2; ++mt)
#pragma unroll
        for (int nt = 0; nt < 12; ++nt)
#pragma unroll
            for (int x = 0; x < 4; ++x) d[mt][nt][x] = 0.f;

    for (int chunk = 0; chunk < 2; ++chunk) {
        __syncthreads();
        // K chunk: [c2 row (64)][k col (384)] bf16 hi/lo
        for (int i = tid; i < 64 * NK; i += 256) {
            int k = i % NK, c2 = i / NK;
            int c = chunk * 64 + c2;
            const float* base;
            int t;
            if (k < 128) { base = kv0 + (size_t)(k >> 6) * IMG; t = k & 63; }
            else { int kk = k - 128; base = kv1 + (size_t)(kk >> 6) * IMG; t = kk & 63; }
            int gy = wy8 + (t >> 3), gx = wx8 + (t & 7);
            float v = base[(size_t)c * HWSZ + gy * WW + gx];
            __nv_bfloat16 h, lo;
            bf16_split(v, h, lo);
            kbf[c2 * 392 + k] = h;
            kbf[25088 + c2 * 392 + k] = lo;
        }
        __syncthreads();

#pragma unroll
        for (int kc = 0; kc < 4; ++kc) {
            uint32_t ah[2][4], al[2][4], bh[6][4], bl[6][4];
#pragma unroll
            for (int mt = 0; mt < 2; ++mt) {
                uint32_t aa = sb + (warp_m * 32 + mt * 16 + (l & 15)) * 272 +
                              chunk * 128 + kc * 32 + (l >> 4) * 16;
                ldsm4(ah[mt], aa);
                ldsm4(al[mt], aa + 17408);
            }
#pragma unroll
            for (int n2 = 0; n2 < 6; ++n2) {
                uint32_t ba = sb + 34816 + (kc * 16 + (l & 15)) * 784 +
                              (warp_n * 96 + n2 * 16) * 2 + (l >> 4) * 16;
                ldsm4t(bh[n2], ba);
                ldsm4t(bl[n2], ba + 50176);
            }
#pragma unroll
            for (int mt = 0; mt < 2; ++mt)
#pragma unroll
                for (int nt = 0; nt < 12; ++nt)
                    mma_bf16(d[mt][nt], ah[mt],
                             bh[nt >> 1][(nt & 1) * 2], bh[nt >> 1][(nt & 1) * 2 + 1]);
#pragma unroll
            for (int mt = 0; mt < 2; ++mt)
#pragma unroll
                for (int nt = 0; nt < 12; ++nt)
                    mma_bf16(d[mt][nt], al[mt],
                             bh[nt >> 1][(nt & 1) * 2], bh[nt >> 1][(nt & 1) * 2 + 1]);
#pragma unroll
            for (int mt = 0; mt < 2; ++mt)
#pragma unroll
                for (int nt = 0; nt < 12; ++nt)
                    mma_bf16(d[mt][nt], ah[mt],
                             bl[nt >> 1][(nt & 1) * 2], bl[nt >> 1][(nt & 1) * 2 + 1]);
        }
    }

    // ---- store S frags -> smem fp32 (aliases dead Q/K)
    __syncthreads();
#pragma unroll
    for (int mt = 0; mt < 2; ++mt)
#pragma unroll
        for (int nt = 0; nt < 12; ++nt) {
            int r0 = warp_m * 32 + mt * 16 + (l >> 2);
            int c0 = warp_n * 96 + nt * 8 + (l & 3) * 2;
            *(float2*)(s_s + (size_t)r0 * SST + c0) =
                make_float2(d[mt][nt][0], d[mt][nt][1]);
            *(float2*)(s_s + (size_t)(r0 + 8) * SST + c0) =
                make_float2(d[mt][nt][2], d[mt][nt][3]);
        }
    __syncthreads();

    // ---- softmax rows (64 threads), mask folded; write P transposed [k][q]
    const float SCALE = 0.08838834764831845f;
    if (tid < 64) {
        float* row = s_s + (size_t)tid * SST;
        float msk = s_m[tid];
        // branch 0: k in [0,128)
        {
            float m0 = -3.4e38f;
            for (int k = 0; k < 128; ++k) m0 = fmaxf(m0, row[k]);
            m0 *= SCALE;
            float sum = 0.f;
            for (int k = 0; k < 128; ++k) {
                float e = __expf(row[k] * SCALE - m0);
                row[k] = e; sum += e;
            }
            float inv = msk / sum;
            for (int k = 0; k < 128; ++k)
                s_p[(size_t)k * PST + tid] = row[k] * inv;
        }
        // branch 1: k in [128,384)
        {
            float m1 = -3.4e38f;
            for (int k = 128; k < 384; ++k) m1 = fmaxf(m1, row[k]);
            m1 *= SCALE;
            float sum = 0.f;
            for (int k = 128; k < 384; ++k) {
                float e = __expf(row[k] * SCALE - m1);
                row[k] = e; sum += e;
            }
            float inv = (1.f - msk) / sum;
            for (int k = 128; k < 384; ++k)
                s_p[(size_t)k * PST + tid] = row[k] * inv;
        }
    }

    // ================= PV scalar (R10 path): 6 chunks of 64 k ===============
    int qb = wid, kidx = l;
    unsigned long long oacc[4][4];
#pragma unroll
    for (int p = 0; p < 4; ++p)
#pragma unroll
        for (int jc = 0; jc < 4; ++jc) oacc[p][jc] = 0ull;

    for (int kc = 0; kc < 6; ++kc) {
        __syncthreads();
        for (int i = tid; i < 64 * CC; i += 256) {
            int kk = i & 63, c = i >> 6;
            int k = kc * 64 + kk;
            const float* base;
            if (k < 128) base = kv0 + (size_t)(k >> 6) * IMG;
            else         base = kv1 + (size_t)((k - 128) >> 6) * IMG;
            int gy = wy8 + (kk >> 3), gx = wx8 + (kk & 7);
            float vv = base[(size_t)c * HWSZ + gy * WW + gx];
            s_v2[kk * VDST + c] = pack2(vv, vv);
        }
        __syncthreads();

#pragma unroll 2
        for (int kk = 0; kk < 64; ++kk) {
            int k = kc * 64 + kk;
            const unsigned long long* pp =
                (const unsigned long long*)(s_p + (size_t)k * PST + qb * 8);
            unsigned long long p0 = pp[0], p1 = pp[1], p2 = pp[2], p3 = pp[3];
            const unsigned long long* vrow = s_v2 + kk * VDST + kidx;
#pragma unroll
            for (int jc = 0; jc < 4; ++jc) {
                unsigned long long v2 = vrow[32 * jc];
                ffma2(oacc[0][jc], p0, v2);
                ffma2(oacc[1][jc], p1, v2);
                ffma2(oacc[2][jc], p2, v2);
                ffma2(oacc[3][jc], p3, v2);
            }
        }
    }

    // ---- transpose O through smem (aliases dead V), residual RMW
    __syncthreads();
    float* s_o = sm;
#pragma unroll
    for (int jc = 0; jc < 4; ++jc) {
        int c = kidx + 32 * jc;
#pragma unroll
        for (int p = 0; p < 4; ++p)
            *(unsigned long long*)(s_o + c * OST + qb * 8 + 2 * p) = oacc[p][jc];
    }
    __syncthreads();
    for (int i = tid; i < 64 * CC; i += 256) {
        int q = i & 63, c = i >> 6;
        int gy = wy8 + (q >> 3), gx = wx8 + (q & 7);
        qimg[(size_t)c * HWSZ + gy * WW + gx] += s_o[c * OST + q];
    }
}

// ---------------------------------------------------------------------------
extern "C" void kernel_launch(void* const* d_in, const int* in_sizes, int n_in,
                              void* d_out, int out_size)
{
    const float* xq   = (const float*)d_in[0];
    const float* xkvw = (const float*)d_in[1];
    const float* xkv  = (const float*)d_in[2];
    const float* em   = (const float*)d_in[3];
    const float* Wq   = (const float*)d_in[4];
    const float* bq   = (const float*)d_in[5];
    const float* aq   = (const float*)d_in[6];
    const float* Wkv  = (const float*)d_in[7];
    const float* bkv  = (const float*)d_in[8];
    const float* akv  = (const float*)d_in[9];
    const float* Wff  = (const float*)d_in[10];
    const float* bff  = (const float*)d_in[11];
    const float* aff  = (const float*)d_in[12];
    float* out = (float*)d_out;

    float *gQ = nullptr, *gKV = nullptr, *gKVw = nullptr;
    float *gV = nullptr, *gM = nullptr, *gU = nullptr;
    cudaGetSymbolAddress((void**)&gQ,   g_Q);
    cudaGetSymbolAddress((void**)&gKV,  g_KV);
    cudaGetSymbolAddress((void**)&gKVw, g_KVw);
    cudaGetSymbolAddress((void**)&gV,   g_V);
    cudaGetSymbolAddress((void**)&gM,   g_M);
    cudaGetSymbolAddress((void**)&gU,   g_U);

    __nv_bfloat16* gVh = (__nv_bfloat16*)gV;
    __nv_bfloat16* gUh = (__nv_bfloat16*)gU;

    cudaFuncSetAttribute(win_attn, cudaFuncAttributeMaxDynamicSharedMemorySize,
                         ATTN_SMEM);
    cudaFuncSetAttribute(wino_gemm_mma,
                         cudaFuncAttributeMaxDynamicSharedMemorySize, GEMM_SMEM);

    dim3 blk(256);

    wino_filt3<<<192, blk>>>(Wq, Wkv, Wff, gUh);

    wino_in14<<<dim3(32, 64, 14), blk>>>(xq, xkv, xkvw, gVh);
    wino_gemm_mma<<<dim3(32, 36, 14), blk, GEMM_SMEM>>>(gVh, gUh, gM, 1);
    wino_out14<<<dim3(16, 64, 14), blk>>>(gM, xq, xkv, xkvw, gQ, gKV, gKVw,
                                          bq, aq, bkv, akv, 1);

    win_attn<<<2048, blk, ATTN_SMEM>>>(gQ, gKV, gKVw, em);

    wino_in<<<dim3(32, 64, 2), blk>>>(gQ, gVh);
    wino_gemm_mma<<<dim3(32, 36, 2), blk, GEMM_SMEM>>>(gVh, gUh, gM, 0);
    wino_out14<<<dim3(16, 64, 2), blk>>>(gM, gQ, gQ, gQ, out, out, out,
                                         bff, aff, bff, aff, 0);
}

// round 13
// speedup vs baseline: 1.3028x; 1.3028x over previous
#include <cuda_runtime.h>
#include <cuda_bf16.h>
#include <cstdint>

#define HH 256
#define WW 256
#define CC 128
#define HWSZ 65536
#define IMG (CC * HH * WW)          // 8388608 floats per frame
#define VIMG (36ull * 128 * 4096)   // transformed plane per image (elems)

// ---------------- scratch (__device__ globals; no allocations) -------------
__device__ float g_Q[2ull * IMG];
__device__ float g_KV[4ull * IMG];
__device__ float g_KVw[8ull * IMG];
__device__ float g_V[14ull * VIMG];      // reused as 2 bf16 planes (hi, lo)
__device__ float g_M[14ull * VIMG];
__device__ float g_U[3ull * 36 * 128 * 128];  // reused as 2 bf16 planes

// ---------------- packed f32x2 helpers --------------------------------------
__device__ __forceinline__ unsigned long long pack2(float x, float y) {
    unsigned long long r;
    asm("mov.b64 %0, {%1,%2};" : "=l"(r) : "f"(x), "f"(y));
    return r;
}
__device__ __forceinline__ void unpack2(unsigned long long v, float& x, float& y) {
    asm("mov.b64 {%0,%1}, %2;" : "=f"(x), "=f"(y) : "l"(v));
}
__device__ __forceinline__ void ffma2(unsigned long long& d,
                                      unsigned long long a,
                                      unsigned long long b) {
    asm("fma.rn.f32x2 %0, %1, %2, %0;" : "+l"(d) : "l"(a), "l"(b));
}

// ---------------- cp.async / ldmatrix / mma helpers -------------------------
__device__ __forceinline__ void cp16(uint32_t saddr, const void* g) {
    asm volatile("cp.async.cg.shared.global [%0], [%1], 16;"
                 :: "r"(saddr), "l"(g) : "memory");
}
#define CP_COMMIT() asm volatile("cp.async.commit_group;" ::: "memory")
#define CP_WAIT(n)  asm volatile("cp.async.wait_group %0;" :: "n"(n) : "memory")

__device__ __forceinline__ uint32_t smem_u32(const void* p) {
    uint32_t a;
    asm("{ .reg .u64 t; cvta.to.shared.u64 t, %1; cvt.u32.u64 %0, t; }"
        : "=r"(a) : "l"(p));
    return a;
}
__device__ __forceinline__ void ldsm4(uint32_t* r, uint32_t a) {
    asm volatile("ldmatrix.sync.aligned.m8n8.x4.shared.b16 {%0,%1,%2,%3}, [%4];"
        : "=r"(r[0]), "=r"(r[1]), "=r"(r[2]), "=r"(r[3]) : "r"(a));
}
__device__ __forceinline__ void ldsm4t(uint32_t* r, uint32_t a) {
    asm volatile("ldmatrix.sync.aligned.m8n8.x4.trans.shared.b16 {%0,%1,%2,%3}, [%4];"
        : "=r"(r[0]), "=r"(r[1]), "=r"(r[2]), "=r"(r[3]) : "r"(a));
}
__device__ __forceinline__ void mma_bf16(float* d, const uint32_t* a,
                                         uint32_t b0, uint32_t b1) {
    asm volatile(
        "mma.sync.aligned.m16n8k16.row.col.f32.bf16.bf16.f32 "
        "{%0,%1,%2,%3}, {%4,%5,%6,%7}, {%8,%9}, {%0,%1,%2,%3};"
        : "+f"(d[0]), "+f"(d[1]), "+f"(d[2]), "+f"(d[3])
        : "r"(a[0]), "r"(a[1]), "r"(a[2]), "r"(a[3]), "r"(b0), "r"(b1));
}

// ---------------- Winograd F(4x4,3x3) transform primitives ------------------
#define BTCOMB(d0,d1,d2,d3,d4,d5,o0,o1,o2,o3,o4,o5) do {                   \
    o0 = 4.f*(d0) - 5.f*(d2) + (d4);                                       \
    float _a = (d4) - 4.f*(d2), _b = (d3) - 4.f*(d1);                      \
    o1 = _a + _b; o2 = _a - _b;                                            \
    float _c = (d4) - (d2), _e = 2.f*((d3) - (d1));                        \
    o3 = _c + _e; o4 = _c - _e;                                            \
    o5 = 4.f*(d1) - 5.f*(d3) + (d5);                                       \
} while (0)

#define ATCOMB(m0,m1,m2,m3,m4,m5,o0,o1,o2,o3) do {                         \
    float _s = (m1)+(m2), _d = (m1)-(m2), _t = (m3)+(m4), _u = (m3)-(m4);  \
    o0 = (m0) + _s + _t;                                                   \
    o1 = _d + 2.f*_u;                                                      \
    o2 = _s + 4.f*_t;                                                      \
    o3 = _d + 8.f*_u + (m5);                                               \
} while (0)

#define GCOMB(w0,w1,w2,o0,o1,o2,o3,o4,o5) do {                             \
    o0 = 0.25f*(w0);                                                       \
    float _n = -(w0) - (w2);                                               \
    o1 = (_n - (w1)) * (1.f/6.f);                                          \
    o2 = (_n + (w1)) * (1.f/6.f);                                          \
    float _p = (w0)*(1.f/24.f) + (w2)*(1.f/6.f), _q = (w1)*(1.f/12.f);     \
    o3 = _p + _q; o4 = _p - _q;                                            \
    o5 = (w2);                                                             \
} while (0)

__device__ __forceinline__ void bf16_split(float v, __nv_bfloat16& h,
                                           __nv_bfloat16& l) {
    h = __float2bfloat16(v);
    l = __float2bfloat16(v - __bfloat162float(h));
}

// ---------------------------------------------------------------------------
// Filter transform -> bf16 hi/lo planes, layout [set][pos][oc][ic]
// ---------------------------------------------------------------------------
__global__ __launch_bounds__(256) void wino_filt3(
    const float* __restrict__ W0, const float* __restrict__ W1,
    const float* __restrict__ W2, __nv_bfloat16* __restrict__ Uh)
{
    __nv_bfloat16* Ul = Uh + 3ull * 36 * 16384;
    int idx = blockIdx.x * 256 + threadIdx.x;
    if (idx >= 3 * 16384) return;
    int set = idx >> 14, e = idx & 16383;
    int oc = e & 127, ic = e >> 7;
    const float* W = (set == 0) ? W0 : (set == 1) ? W1 : W2;
    size_t soff = (size_t)set * (36 * 16384);
    float w[3][3];
#pragma unroll
    for (int a = 0; a < 3; ++a)
#pragma unroll
        for (int b = 0; b < 3; ++b)
            w[a][b] = W[(size_t)oc * 1152 + ic * 9 + a * 3 + b];
    float ee[6][3];
#pragma unroll
    for (int b = 0; b < 3; ++b)
        GCOMB(w[0][b], w[1][b], w[2][b],
              ee[0][b], ee[1][b], ee[2][b], ee[3][b], ee[4][b], ee[5][b]);
#pragma unroll
    for (int i = 0; i < 6; ++i) {
        float u[6];
        GCOMB(ee[i][0], ee[i][1], ee[i][2], u[0], u[1], u[2], u[3], u[4], u[5]);
#pragma unroll
        for (int j = 0; j < 6; ++j) {
            size_t off = soff + (size_t)(i * 6 + j) * 16384 + oc * 128 + ic;
            __nv_bfloat16 h, l;
            bf16_split(u[j], h, l);
            Uh[off] = h; Ul[off] = l;
        }
    }
}

// ---------------------------------------------------------------------------
// Merged input transform -> bf16 hi/lo V planes [img][pos][ic][tile]
// ---------------------------------------------------------------------------
__global__ __launch_bounds__(256) void wino_in14(
    const float* __restrict__ xq, const float* __restrict__ xkv,
    const float* __restrict__ xkvw, __nv_bfloat16* __restrict__ vh)
{
    __nv_bfloat16* vl = vh + 14ull * VIMG;
    __shared__ __align__(16) float s_d[4][6][264];
    int img = blockIdx.z, ty = blockIdx.y, c4 = blockIdx.x;
    int tid = threadIdx.x;
    const float* xb;
    if (img < 2)      xb = xq   + (size_t)img * IMG;
    else if (img < 6) xb = xkv  + (size_t)(img - 2) * IMG;
    else              xb = xkvw + (size_t)(img - 6) * IMG;
    xb += (size_t)(c4 * 4) * HWSZ;

    for (int i = tid; i < 4 * 6 * 258; i += 256) {
        int c = i / (6 * 258);
        int rem = i - c * (6 * 258);
        int r = rem / 258, col = rem - r * 258;
        int gy = ty * 4 - 1 + r, gx = col - 1;
        float v = 0.f;
        if ((unsigned)gy < 256u && (unsigned)gx < 256u)
            v = xb[(size_t)c * HWSZ + gy * 256 + gx];
        s_d[c][r][col] = v;
    }
    __syncthreads();

    int tx = tid & 63, c = tid >> 6;
    float d[6][6];
#pragma unroll
    for (int r = 0; r < 6; ++r) {
        const float4* row = (const float4*)s_d[c][r];
        float4 a = row[tx], b = row[tx + 1];
        d[r][0] = a.x; d[r][1] = a.y; d[r][2] = a.z;
        d[r][3] = a.w; d[r][4] = b.x; d[r][5] = b.y;
    }
    float e[6][6];
#pragma unroll
    for (int j = 0; j < 6; ++j)
        BTCOMB(d[0][j], d[1][j], d[2][j], d[3][j], d[4][j], d[5][j],
               e[0][j], e[1][j], e[2][j], e[3][j], e[4][j], e[5][j]);

    size_t base = (size_t)img * VIMG + (size_t)(c4 * 4 + c) * 4096 +
                  ty * 64 + tx;
#pragma unroll
    for (int i = 0; i < 6; ++i) {
        float o[6];
        BTCOMB(e[i][0], e[i][1], e[i][2], e[i][3], e[i][4], e[i][5],
               o[0], o[1], o[2], o[3], o[4], o[5]);
#pragma unroll
        for (int j = 0; j < 6; ++j) {
            size_t off = base + (size_t)(i * 6 + j) * 524288;
            __nv_bfloat16 h, l;
            bf16_split(o[j], h, l);
            vh[off] = h; vl[off] = l;
        }
    }
}

// FF-stage input transform (2 images from gQ)
__global__ __launch_bounds__(256) void wino_in(
    const float* __restrict__ x, __nv_bfloat16* __restrict__ vh)
{
    __nv_bfloat16* vl = vh + 14ull * VIMG;
    __shared__ __align__(16) float s_d[4][6][264];
    int img = blockIdx.z, ty = blockIdx.y, c4 = blockIdx.x;
    int tid = threadIdx.x;
    const float* xb = x + (size_t)img * IMG + (size_t)(c4 * 4) * HWSZ;

    for (int i = tid; i < 4 * 6 * 258; i += 256) {
        int c = i / (6 * 258);
        int rem = i - c * (6 * 258);
        int r = rem / 258, col = rem - r * 258;
        int gy = ty * 4 - 1 + r, gx = col - 1;
        float v = 0.f;
        if ((unsigned)gy < 256u && (unsigned)gx < 256u)
            v = xb[(size_t)c * HWSZ + gy * 256 + gx];
        s_d[c][r][col] = v;
    }
    __syncthreads();

    int tx = tid & 63, c = tid >> 6;
    float d[6][6];
#pragma unroll
    for (int r = 0; r < 6; ++r) {
        const float4* row = (const float4*)s_d[c][r];
        float4 a = row[tx], b = row[tx + 1];
        d[r][0] = a.x; d[r][1] = a.y; d[r][2] = a.z;
        d[r][3] = a.w; d[r][4] = b.x; d[r][5] = b.y;
    }
    float e[6][6];
#pragma unroll
    for (int j = 0; j < 6; ++j)
        BTCOMB(d[0][j], d[1][j], d[2][j], d[3][j], d[4][j], d[5][j],
               e[0][j], e[1][j], e[2][j], e[3][j], e[4][j], e[5][j]);

    size_t base = (size_t)img * VIMG + (size_t)(c4 * 4 + c) * 4096 +
                  ty * 64 + tx;
#pragma unroll
    for (int i = 0; i < 6; ++i) {
        float o[6];
        BTCOMB(e[i][0], e[i][1], e[i][2], e[i][3], e[i][4], e[i][5],
               o[0], o[1], o[2], o[3], o[4], o[5]);
#pragma unroll
        for (int j = 0; j < 6; ++j) {
            size_t off = base + (size_t)(i * 6 + j) * 524288;
            __nv_bfloat16 h, l;
            bf16_split(o[j], h, l);
            vh[off] = h; vl[off] = l;
        }
    }
}

// ---------------------------------------------------------------------------
// Winograd GEMM via mma.sync (HMMA) + bf16 3-term split.  (R11 passing version)
// ---------------------------------------------------------------------------
#define GEMM_SMEM 75776
#define AS_STAGE 20480
#define AS_TERM  10240
#define BS_BASE  40960
#define BS_STAGE 17408
#define BS_TERM  8704

__global__ __launch_bounds__(256, 1) void wino_gemm_mma(
    const __nv_bfloat16* __restrict__ vh, const __nv_bfloat16* __restrict__ uh,
    float* __restrict__ mout, int route)
{
    extern __shared__ __align__(16) char smx[];
    const __nv_bfloat16* vl = vh + 14ull * VIMG;
    const __nv_bfloat16* ul = uh + 3ull * 36 * 16384;

    int pos = blockIdx.y, img = blockIdx.z, tb = blockIdx.x;
    int tid = threadIdx.x, l = tid & 31, wid = tid >> 5;
    int warp_m = wid & 1, warp_n = wid >> 1;

    int uset = route ? ((img < 2) ? 0 : 1) : 2;
    size_t uoff = (size_t)uset * (36 * 16384) + (size_t)pos * 16384;
    size_t voff = (size_t)img * VIMG + (size_t)pos * 524288 + tb * 128;

    uint32_t sb = smem_u32(smx);

#define COPY_CHUNK(chunk, buf) do {                                         \
    int _ic0 = (chunk) * 32;                                                \
    _Pragma("unroll")                                                       \
    for (int _i = 0; _i < 4; ++_i) {                                        \
        int _t = tid + _i * 256;                                            \
        int _term = _t >> 9, _r = (_t >> 2) & 127, _s = _t & 3;             \
        const __nv_bfloat16* _src =                                         \
            (_term ? ul : uh) + uoff + _r * 128 + _ic0 + _s * 8;            \
        cp16(sb + (buf) * AS_STAGE + _term * AS_TERM + _r * 80 + _s * 16,   \
             _src);                                                         \
        int _bt = _t >> 9, _rem = _t & 511, _br = _rem >> 4, _bs = _rem & 15;\
        const __nv_bfloat16* _bsrc =                                        \
            (_bt ? vl : vh) + voff + (size_t)(_ic0 + _br) * 4096 + _bs * 8; \
        cp16(sb + BS_BASE + (buf) * BS_STAGE + _bt * BS_TERM +              \
             _br * 272 + _bs * 16, _bsrc);                                  \
    }                                                                       \
    CP_COMMIT();                                                            \
} while (0)

    float d[4][4][4];
#pragma unroll
    for (int mt = 0; mt < 4; ++mt)
#pragma unroll
        for (int nt = 0; nt < 4; ++nt)
#pragma unroll
            for (int k = 0; k < 4; ++k) d[mt][nt][k] = 0.f;

    COPY_CHUNK(0, 0);

    for (int c = 0; c < 4; ++c) {
        int buf = c & 1;
        if (c < 3) {
            COPY_CHUNK(c + 1, buf ^ 1);
            CP_WAIT(1);
        } else {
            CP_WAIT(0);
        }
        __syncthreads();

#pragma unroll
        for (int ks = 0; ks < 2; ++ks) {
            uint32_t ah[4][4], al[4][4], bh[2][4], bl[2][4];
#pragma unroll
            for (int mt = 0; mt < 4; ++mt) {
                uint32_t aa = sb + buf * AS_STAGE +
                    (warp_m * 64 + mt * 16 + (l & 15)) * 80 +
                    ks * 32 + (l >> 4) * 16;
                ldsm4(ah[mt], aa);
                ldsm4(al[mt], aa + AS_TERM);
            }
#pragma unroll
            for (int n2 = 0; n2 < 2; ++n2) {
                uint32_t ba = sb + BS_BASE + buf * BS_STAGE +
                    (ks * 16 + (l & 7) + ((l >> 3) & 1) * 8) * 272 +
                    (warp_n * 32 + n2 * 16) * 2 + (l >> 4) * 16;
                ldsm4t(bh[n2], ba);
                ldsm4t(bl[n2], ba + BS_TERM);
            }
#pragma unroll
            for (int mt = 0; mt < 4; ++mt)
#pragma unroll
                for (int nt = 0; nt < 4; ++nt)
                    mma_bf16(d[mt][nt], ah[mt],
                             bh[nt >> 1][(nt & 1) * 2], bh[nt >> 1][(nt & 1) * 2 + 1]);
#pragma unroll
            for (int mt = 0; mt < 4; ++mt)
#pragma unroll
                for (int nt = 0; nt < 4; ++nt)
                    mma_bf16(d[mt][nt], al[mt],
                             bh[nt >> 1][(nt & 1) * 2], bh[nt >> 1][(nt & 1) * 2 + 1]);
#pragma unroll
            for (int mt = 0; mt < 4; ++mt)
#pragma unroll
                for (int nt = 0; nt < 4; ++nt)
                    mma_bf16(d[mt][nt], ah[mt],
                             bl[nt >> 1][(nt & 1) * 2], bl[nt >> 1][(nt & 1) * 2 + 1]);
        }
        __syncthreads();
    }

    float* Mo = mout + (size_t)img * VIMG + (size_t)pos * 524288 + tb * 128;
#pragma unroll
    for (int mt = 0; mt < 4; ++mt)
#pragma unroll
        for (int nt = 0; nt < 4; ++nt) {
            int oc0 = warp_m * 64 + mt * 16 + (l >> 2);
            int t0  = warp_n * 32 + nt * 8 + (l & 3) * 2;
            float2 v01 = make_float2(d[mt][nt][0], d[mt][nt][1]);
            float2 v23 = make_float2(d[mt][nt][2], d[mt][nt][3]);
            *(float2*)(Mo + (size_t)oc0 * 4096 + t0) = v01;
            *(float2*)(Mo + (size_t)(oc0 + 8) * 4096 + t0) = v23;
        }
#undef COPY_CHUNK
}

// ---------------------------------------------------------------------------
// Merged output transform + bias + PReLU + residual, per-image routing.
// ---------------------------------------------------------------------------
__global__ __launch_bounds__(256) void wino_out14(
    const float* __restrict__ mout,
    const float* __restrict__ r0, const float* __restrict__ r1,
    const float* __restrict__ r2,
    float* __restrict__ y0, float* __restrict__ y1, float* __restrict__ y2,
    const float* __restrict__ bias0, const float* __restrict__ alpha0,
    const float* __restrict__ bias1, const float* __restrict__ alpha1,
    int route)
{
    __shared__ __align__(16) float s_o[8][4][256];
    int img = blockIdx.z, ty = blockIdx.y, og = blockIdx.x;
    int tid = threadIdx.x;

    const float* resid; float* y; const float* bias; const float* alpha;
    if (!route || img < 2) {
        resid = r0 + (size_t)img * IMG; y = y0 + (size_t)img * IMG;
        bias = bias0; alpha = alpha0;
    } else if (img < 6) {
        resid = r1 + (size_t)(img - 2) * IMG; y = y1 + (size_t)(img - 2) * IMG;
        bias = bias1; alpha = alpha1;
    } else {
        resid = r2 + (size_t)(img - 6) * IMG; y = y2 + (size_t)(img - 6) * IMG;
        bias = bias1; alpha = alpha1;
    }

#pragma unroll
    for (int it = 0; it < 2; ++it) {
        int item = tid + it * 256;
        int tx = item & 63, ol = item >> 6;
        const float* Mp = mout + (size_t)img * VIMG +
                          (size_t)(og * 8 + ol) * 4096 + ty * 64 + tx;
        float m[6][6];
#pragma unroll
        for (int pos = 0; pos < 36; ++pos)
            m[pos / 6][pos % 6] = Mp[(size_t)pos * 524288];
        float e[4][6];
#pragma unroll
        for (int j = 0; j < 6; ++j)
            ATCOMB(m[0][j], m[1][j], m[2][j], m[3][j], m[4][j], m[5][j],
                   e[0][j], e[1][j], e[2][j], e[3][j]);
#pragma unroll
        for (int r = 0; r < 4; ++r) {
            float o0, o1, o2, o3;
            ATCOMB(e[r][0], e[r][1], e[r][2], e[r][3], e[r][4], e[r][5],
                   o0, o1, o2, o3);
            ((float4*)s_o[ol][r])[tx] = make_float4(o0, o1, o2, o3);
        }
    }
    __syncthreads();

    float a = alpha[0];
    for (int i = tid; i < 8192; i += 256) {
        int ol = i >> 10, rem = i & 1023, r = rem >> 8, px = rem & 255;
        int oc = og * 8 + ol;
        int gy = ty * 4 + r;
        size_t addr = (size_t)oc * HWSZ + gy * 256 + px;
        float v = s_o[ol][r][px] + bias[oc];
        v = (v >= 0.f) ? v : a * v;
        y[addr] = resid[addr] + v;
    }
}

// ---------------------------------------------------------------------------
// Windowed dual-branch attention v5: QK via HMMA (spill-safe scheduling),
// parallel softmax (128 independent row-branch tasks), scalar FFMA2 PV.
// smem bytes: Qhi[0,17408) Qlo[17408,34816) Khi[34816,84992) Klo[84992,135168)
//   S fp32 [64][392] aliases [0,100352); P fp32 [384][66] at [100352,201728)
//   Vdup ull [64][129] aliases [0,66048); mask at [201728,201984)
// ---------------------------------------------------------------------------
#define SST 392
#define PST 66
#define VDST 129
#define OST 66
#define OFF_P 25088
#define OFF_SM 50432
#define ATTN_SMEM 201984
#define NK 384

__global__ __launch_bounds__(256, 1) void win_attn(
    float* __restrict__ Qbuf, const float* __restrict__ KV,
    const float* __restrict__ KVw, const float* __restrict__ em)
{
    extern __shared__ __align__(16) float sm[];
    __nv_bfloat16* qbf = (__nv_bfloat16*)sm;
    __nv_bfloat16* kbf = (__nv_bfloat16*)sm + 17408;
    float* s_s = sm;
    float* s_p = sm + OFF_P;
    unsigned long long* s_v2 = (unsigned long long*)sm;
    float* s_m = sm + OFF_SM;

    int bwin = blockIdx.x;
    int bb  = bwin >> 10;
    int wy8 = ((bwin >> 5) & 31) << 3;
    int wx8 = (bwin & 31) << 3;
    int tid = threadIdx.x;
    int l = tid & 31, wid = tid >> 5;
    int warp_m = wid & 1, warp_n = wid >> 1;
    uint32_t sb = smem_u32(sm);

    float* qimg = Qbuf + (size_t)bb * IMG;
    const float* kv0 = KV + (size_t)bb * 2 * IMG;
    const float* kv1 = KVw + (size_t)bb * 4 * IMG;

    // ---- load Q as bf16 hi/lo [q row][c col] (272B rows)
    for (int i = tid; i < 64 * CC; i += 256) {
        int q = i & 63, c = i >> 6;
        int gy = wy8 + (q >> 3), gx = wx8 + (q & 7);
        float v = qimg[(size_t)c * HWSZ + gy * WW + gx];
        __nv_bfloat16 h, lo;
        bf16_split(v, h, lo);
        qbf[q * 136 + c] = h;
        qbf[8704 + q * 136 + c] = lo;
    }
    if (tid < 64) {
        int gy = wy8 + (tid >> 3), gx = wx8 + (tid & 7);
        s_m[tid] = em[(size_t)bb * HWSZ + gy * WW + gx];
    }

    // ================= QK via HMMA (3-term), 2 chunks of 64 channels ========
    float d[2][12][4];
#pragma unroll
    for (int mt = 0; mt < 2; ++mt)
#pragma unroll
        for (int nt = 0; nt < 12; ++nt)
#pragma unroll
            for (int x = 0; x < 4; ++x) d[mt][nt][x] = 0.f;

    for (int chunk = 0; chunk < 2; ++chunk) {
        __syncthreads();
        for (int i = tid; i < 64 * NK; i += 256) {
            int k = i % NK, c2 = i / NK;
            int c = chunk * 64 + c2;
            const float* base;
            int t;
            if (k < 128) { base = kv0 + (size_t)(k >> 6) * IMG; t = k & 63; }
            else { int kk = k - 128; base = kv1 + (size_t)(kk >> 6) * IMG; t = kk & 63; }
            int gy = wy8 + (t >> 3), gx = wx8 + (t & 7);
            float v = base[(size_t)c * HWSZ + gy * WW + gx];
            __nv_bfloat16 h, lo;
            bf16_split(v, h, lo);
            kbf[c2 * 392 + k] = h;
            kbf[25088 + c2 * 392 + k] = lo;
        }
        __syncthreads();

#pragma unroll
        for (int kc = 0; kc < 4; ++kc) {
            uint32_t ah[2][4], al[2][4];
#pragma unroll
            for (int mt = 0; mt < 2; ++mt) {
                uint32_t aa = sb + (warp_m * 32 + mt * 16 + (l & 15)) * 272 +
                              chunk * 128 + kc * 32 + (l >> 4) * 16;
                ldsm4(ah[mt], aa);
                ldsm4(al[mt], aa + 17408);
            }
            // B fragments loaded ONE n2 at a time (spill-safe)
#pragma unroll
            for (int n2 = 0; n2 < 6; ++n2) {
                uint32_t bh[4], bl[4];
                uint32_t ba = sb + 34816 + (kc * 16 + (l & 15)) * 784 +
                              (warp_n * 96 + n2 * 16) * 2 + (l >> 4) * 16;
                ldsm4t(bh, ba);
                ldsm4t(bl, ba + 50176);
#pragma unroll
                for (int mt = 0; mt < 2; ++mt) {
                    float* d0 = d[mt][n2 * 2];
                    float* d1 = d[mt][n2 * 2 + 1];
                    mma_bf16(d0, ah[mt], bh[0], bh[1]);
                    mma_bf16(d1, ah[mt], bh[2], bh[3]);
                    mma_bf16(d0, al[mt], bh[0], bh[1]);
                    mma_bf16(d1, al[mt], bh[2], bh[3]);
                    mma_bf16(d0, ah[mt], bl[0], bl[1]);
                    mma_bf16(d1, ah[mt], bl[2], bl[3]);
                }
            }
        }
    }

    // ---- store S frags -> smem fp32 (aliases dead Q/K)
    __syncthreads();
#pragma unroll
    for (int mt = 0; mt < 2; ++mt)
#pragma unroll
        for (int nt = 0; nt < 12; ++nt) {
            int r0 = warp_m * 32 + mt * 16 + (l >> 2);
            int c0 = warp_n * 96 + nt * 8 + (l & 3) * 2;
            *(float2*)(s_s + (size_t)r0 * SST + c0) =
                make_float2(d[mt][nt][0], d[mt][nt][1]);
            *(float2*)(s_s + (size_t)(r0 + 8) * SST + c0) =
                make_float2(d[mt][nt][2], d[mt][nt][3]);
        }
    __syncthreads();

    // ---- parallel softmax: 128 tasks = 64 rows x 2 independent branches
    const float SCALE = 0.08838834764831845f;
    if (tid < 128) {
        int r = tid & 63, br = tid >> 6;
        float* row = s_s + (size_t)r * SST;
        float msk = s_m[r];
        int k0 = br ? 128 : 0, k1 = br ? 384 : 128;
        float m0 = -3.4e38f, m1 = -3.4e38f;
        for (int k = k0; k < k1; k += 2) {
            m0 = fmaxf(m0, row[k]);
            m1 = fmaxf(m1, row[k + 1]);
        }
        float m = fmaxf(m0, m1) * SCALE;
        float s0 = 0.f, s1 = 0.f;
        for (int k = k0; k < k1; k += 2) {
            float e0 = __expf(row[k] * SCALE - m);
            float e1 = __expf(row[k + 1] * SCALE - m);
            row[k] = e0; row[k + 1] = e1;
            s0 += e0; s1 += e1;
        }
        float wgt = br ? (1.f - msk) : msk;
        float inv = wgt / (s0 + s1);
        for (int k = k0; k < k1; ++k)
            s_p[(size_t)k * PST + r] = row[k] * inv;
    }

    // ================= PV scalar: 6 chunks of 64 k ==========================
    int qb = wid, kidx = l;
    unsigned long long oacc[4][4];
#pragma unroll
    for (int p = 0; p < 4; ++p)
#pragma unroll
        for (int jc = 0; jc < 4; ++jc) oacc[p][jc] = 0ull;

    for (int kc = 0; kc < 6; ++kc) {
        __syncthreads();
        for (int i = tid; i < 64 * CC; i += 256) {
            int kk = i & 63, c = i >> 6;
            int k = kc * 64 + kk;
            const float* base;
            if (k < 128) base = kv0 + (size_t)(k >> 6) * IMG;
            else         base = kv1 + (size_t)((k - 128) >> 6) * IMG;
            int gy = wy8 + (kk >> 3), gx = wx8 + (kk & 7);
            float vv = base[(size_t)c * HWSZ + gy * WW + gx];
            s_v2[kk * VDST + c] = pack2(vv, vv);
        }
        __syncthreads();

#pragma unroll 2
        for (int kk = 0; kk < 64; ++kk) {
            int k = kc * 64 + kk;
            const unsigned long long* pp =
                (const unsigned long long*)(s_p + (size_t)k * PST + qb * 8);
            unsigned long long p0 = pp[0], p1 = pp[1], p2 = pp[2], p3 = pp[3];
            const unsigned long long* vrow = s_v2 + kk * VDST + kidx;
#pragma unroll
            for (int jc = 0; jc < 4; ++jc) {
                unsigned long long v2 = vrow[32 * jc];
                ffma2(oacc[0][jc], p0, v2);
                ffma2(oacc[1][jc], p1, v2);
                ffma2(oacc[2][jc], p2, v2);
                ffma2(oacc[3][jc], p3, v2);
            }
        }
    }

    // ---- transpose O through smem (aliases dead V), residual RMW
    __syncthreads();
    float* s_o = sm;
#pragma unroll
    for (int jc = 0; jc < 4; ++jc) {
        int c = kidx + 32 * jc;
#pragma unroll
        for (int p = 0; p < 4; ++p)
            *(unsigned long long*)(s_o + c * OST + qb * 8 + 2 * p) = oacc[p][jc];
    }
    __syncthreads();
    for (int i = tid; i < 64 * CC; i += 256) {
        int q = i & 63, c = i >> 6;
        int gy = wy8 + (q >> 3), gx = wx8 + (q & 7);
        qimg[(size_t)c * HWSZ + gy * WW + gx] += s_o[c * OST + q];
    }
}

// ---------------------------------------------------------------------------
extern "C" void kernel_launch(void* const* d_in, const int* in_sizes, int n_in,
                              void* d_out, int out_size)
{
    const float* xq   = (const float*)d_in[0];
    const float* xkvw = (const float*)d_in[1];
    const float* xkv  = (const float*)d_in[2];
    const float* em   = (const float*)d_in[3];
    const float* Wq   = (const float*)d_in[4];
    const float* bq   = (const float*)d_in[5];
    const float* aq   = (const float*)d_in[6];
    const float* Wkv  = (const float*)d_in[7];
    const float* bkv  = (const float*)d_in[8];
    const float* akv  = (const float*)d_in[9];
    const float* Wff  = (const float*)d_in[10];
    const float* bff  = (const float*)d_in[11];
    const float* aff  = (const float*)d_in[12];
    float* out = (float*)d_out;

    float *gQ = nullptr, *gKV = nullptr, *gKVw = nullptr;
    float *gV = nullptr, *gM = nullptr, *gU = nullptr;
    cudaGetSymbolAddress((void**)&gQ,   g_Q);
    cudaGetSymbolAddress((void**)&gKV,  g_KV);
    cudaGetSymbolAddress((void**)&gKVw, g_KVw);
    cudaGetSymbolAddress((void**)&gV,   g_V);
    cudaGetSymbolAddress((void**)&gM,   g_M);
    cudaGetSymbolAddress((void**)&gU,   g_U);

    __nv_bfloat16* gVh = (__nv_bfloat16*)gV;
    __nv_bfloat16* gUh = (__nv_bfloat16*)gU;

    cudaFuncSetAttribute(win_attn, cudaFuncAttributeMaxDynamicSharedMemorySize,
                         ATTN_SMEM);
    cudaFuncSetAttribute(wino_gemm_mma,
                         cudaFuncAttributeMaxDynamicSharedMemorySize, GEMM_SMEM);

    dim3 blk(256);

    wino_filt3<<<192, blk>>>(Wq, Wkv, Wff, gUh);

    wino_in14<<<dim3(32, 64, 14), blk>>>(xq, xkv, xkvw, gVh);
    wino_gemm_mma<<<dim3(32, 36, 14), blk, GEMM_SMEM>>>(gVh, gUh, gM, 1);
    wino_out14<<<dim3(16, 64, 14), blk>>>(gM, xq, xkv, xkvw, gQ, gKV, gKVw,
                                          bq, aq, bkv, akv, 1);

    win_attn<<<2048, blk, ATTN_SMEM>>>(gQ, gKV, gKVw, em);

    wino_in<<<dim3(32, 64, 2), blk>>>(gQ, gVh);
    wino_gemm_mma<<<dim3(32, 36, 2), blk, GEMM_SMEM>>>(gVh, gUh, gM, 0);
    wino_out14<<<dim3(16, 64, 2), blk>>>(gM, gQ, gQ, gQ, out, out, out,
                                         bff, aff, bff, aff, 0);
}

// round 14
// speedup vs baseline: 1.3277x; 1.0191x over previous
#include <cuda_runtime.h>
#include <cuda_bf16.h>
#include <cstdint>

#define HH 256
#define WW 256
#define CC 128
#define HWSZ 65536
#define IMG (CC * HH * WW)          // 8388608 floats per frame
#define VIMG (36ull * 128 * 4096)   // transformed plane per image (elems)

// ---------------- scratch (__device__ globals; no allocations) -------------
__device__ float g_Q[2ull * IMG];
__device__ float g_KV[4ull * IMG];
__device__ float g_KVw[8ull * IMG];
__device__ float g_V[14ull * VIMG];      // reused as 2 bf16 planes (hi, lo)
__device__ float g_M[14ull * VIMG];
__device__ float g_U[3ull * 36 * 128 * 128];  // reused as 2 bf16 planes

// ---------------- packed f32x2 helpers --------------------------------------
__device__ __forceinline__ unsigned long long pack2(float x, float y) {
    unsigned long long r;
    asm("mov.b64 %0, {%1,%2};" : "=l"(r) : "f"(x), "f"(y));
    return r;
}
__device__ __forceinline__ void unpack2(unsigned long long v, float& x, float& y) {
    asm("mov.b64 {%0,%1}, %2;" : "=f"(x), "=f"(y) : "l"(v));
}
__device__ __forceinline__ void ffma2(unsigned long long& d,
                                      unsigned long long a,
                                      unsigned long long b) {
    asm("fma.rn.f32x2 %0, %1, %2, %0;" : "+l"(d) : "l"(a), "l"(b));
}

// ---------------- cp.async / ldmatrix / mma helpers -------------------------
__device__ __forceinline__ void cp16(uint32_t saddr, const void* g) {
    asm volatile("cp.async.cg.shared.global [%0], [%1], 16;"
                 :: "r"(saddr), "l"(g) : "memory");
}
#define CP_COMMIT() asm volatile("cp.async.commit_group;" ::: "memory")
#define CP_WAIT(n)  asm volatile("cp.async.wait_group %0;" :: "n"(n) : "memory")

__device__ __forceinline__ uint32_t smem_u32(const void* p) {
    uint32_t a;
    asm("{ .reg .u64 t; cvta.to.shared.u64 t, %1; cvt.u32.u64 %0, t; }"
        : "=r"(a) : "l"(p));
    return a;
}
__device__ __forceinline__ void ldsm4(uint32_t* r, uint32_t a) {
    asm volatile("ldmatrix.sync.aligned.m8n8.x4.shared.b16 {%0,%1,%2,%3}, [%4];"
        : "=r"(r[0]), "=r"(r[1]), "=r"(r[2]), "=r"(r[3]) : "r"(a));
}
__device__ __forceinline__ void ldsm4t(uint32_t* r, uint32_t a) {
    asm volatile("ldmatrix.sync.aligned.m8n8.x4.trans.shared.b16 {%0,%1,%2,%3}, [%4];"
        : "=r"(r[0]), "=r"(r[1]), "=r"(r[2]), "=r"(r[3]) : "r"(a));
}
__device__ __forceinline__ void mma_bf16(float* d, const uint32_t* a,
                                         uint32_t b0, uint32_t b1) {
    asm volatile(
        "mma.sync.aligned.m16n8k16.row.col.f32.bf16.bf16.f32 "
        "{%0,%1,%2,%3}, {%4,%5,%6,%7}, {%8,%9}, {%0,%1,%2,%3};"
        : "+f"(d[0]), "+f"(d[1]), "+f"(d[2]), "+f"(d[3])
        : "r"(a[0]), "r"(a[1]), "r"(a[2]), "r"(a[3]), "r"(b0), "r"(b1));
}

// ---------------- Winograd F(4x4,3x3) transform primitives ------------------
#define BTCOMB(d0,d1,d2,d3,d4,d5,o0,o1,o2,o3,o4,o5) do {                   \
    o0 = 4.f*(d0) - 5.f*(d2) + (d4);                                       \
    float _a = (d4) - 4.f*(d2), _b = (d3) - 4.f*(d1);                      \
    o1 = _a + _b; o2 = _a - _b;                                            \
    float _c = (d4) - (d2), _e = 2.f*((d3) - (d1));                        \
    o3 = _c + _e; o4 = _c - _e;                                            \
    o5 = 4.f*(d1) - 5.f*(d3) + (d5);                                       \
} while (0)

#define ATCOMB(m0,m1,m2,m3,m4,m5,o0,o1,o2,o3) do {                         \
    float _s = (m1)+(m2), _d = (m1)-(m2), _t = (m3)+(m4), _u = (m3)-(m4);  \
    o0 = (m0) + _s + _t;                                                   \
    o1 = _d + 2.f*_u;                                                      \
    o2 = _s + 4.f*_t;                                                      \
    o3 = _d + 8.f*_u + (m5);                                               \
} while (0)

#define GCOMB(w0,w1,w2,o0,o1,o2,o3,o4,o5) do {                             \
    o0 = 0.25f*(w0);                                                       \
    float _n = -(w0) - (w2);                                               \
    o1 = (_n - (w1)) * (1.f/6.f);                                          \
    o2 = (_n + (w1)) * (1.f/6.f);                                          \
    float _p = (w0)*(1.f/24.f) + (w2)*(1.f/6.f), _q = (w1)*(1.f/12.f);     \
    o3 = _p + _q; o4 = _p - _q;                                            \
    o5 = (w2);                                                             \
} while (0)

__device__ __forceinline__ void bf16_split(float v, __nv_bfloat16& h,
                                           __nv_bfloat16& l) {
    h = __float2bfloat16(v);
    l = __float2bfloat16(v - __bfloat162float(h));
}

// ---------------------------------------------------------------------------
// Filter transform -> bf16 hi/lo planes, layout [set][pos][oc][ic]
// ---------------------------------------------------------------------------
__global__ __launch_bounds__(256) void wino_filt3(
    const float* __restrict__ W0, const float* __restrict__ W1,
    const float* __restrict__ W2, __nv_bfloat16* __restrict__ Uh)
{
    __nv_bfloat16* Ul = Uh + 3ull * 36 * 16384;
    int idx = blockIdx.x * 256 + threadIdx.x;
    if (idx >= 3 * 16384) return;
    int set = idx >> 14, e = idx & 16383;
    int oc = e & 127, ic = e >> 7;
    const float* W = (set == 0) ? W0 : (set == 1) ? W1 : W2;
    size_t soff = (size_t)set * (36 * 16384);
    float w[3][3];
#pragma unroll
    for (int a = 0; a < 3; ++a)
#pragma unroll
        for (int b = 0; b < 3; ++b)
            w[a][b] = W[(size_t)oc * 1152 + ic * 9 + a * 3 + b];
    float ee[6][3];
#pragma unroll
    for (int b = 0; b < 3; ++b)
        GCOMB(w[0][b], w[1][b], w[2][b],
              ee[0][b], ee[1][b], ee[2][b], ee[3][b], ee[4][b], ee[5][b]);
#pragma unroll
    for (int i = 0; i < 6; ++i) {
        float u[6];
        GCOMB(ee[i][0], ee[i][1], ee[i][2], u[0], u[1], u[2], u[3], u[4], u[5]);
#pragma unroll
        for (int j = 0; j < 6; ++j) {
            size_t off = soff + (size_t)(i * 6 + j) * 16384 + oc * 128 + ic;
            __nv_bfloat16 h, l;
            bf16_split(u[j], h, l);
            Uh[off] = h; Ul[off] = l;
        }
    }
}

// ---------------------------------------------------------------------------
// Merged input transform -> bf16 hi/lo V planes [img][pos][ic][tile]
// ---------------------------------------------------------------------------
__global__ __launch_bounds__(256) void wino_in14(
    const float* __restrict__ xq, const float* __restrict__ xkv,
    const float* __restrict__ xkvw, __nv_bfloat16* __restrict__ vh)
{
    __nv_bfloat16* vl = vh + 14ull * VIMG;
    __shared__ __align__(16) float s_d[4][6][264];
    int img = blockIdx.z, ty = blockIdx.y, c4 = blockIdx.x;
    int tid = threadIdx.x;
    const float* xb;
    if (img < 2)      xb = xq   + (size_t)img * IMG;
    else if (img < 6) xb = xkv  + (size_t)(img - 2) * IMG;
    else              xb = xkvw + (size_t)(img - 6) * IMG;
    xb += (size_t)(c4 * 4) * HWSZ;

    for (int i = tid; i < 4 * 6 * 258; i += 256) {
        int c = i / (6 * 258);
        int rem = i - c * (6 * 258);
        int r = rem / 258, col = rem - r * 258;
        int gy = ty * 4 - 1 + r, gx = col - 1;
        float v = 0.f;
        if ((unsigned)gy < 256u && (unsigned)gx < 256u)
            v = xb[(size_t)c * HWSZ + gy * 256 + gx];
        s_d[c][r][col] = v;
    }
    __syncthreads();

    int tx = tid & 63, c = tid >> 6;
    float d[6][6];
#pragma unroll
    for (int r = 0; r < 6; ++r) {
        const float4* row = (const float4*)s_d[c][r];
        float4 a = row[tx], b = row[tx + 1];
        d[r][0] = a.x; d[r][1] = a.y; d[r][2] = a.z;
        d[r][3] = a.w; d[r][4] = b.x; d[r][5] = b.y;
    }
    float e[6][6];
#pragma unroll
    for (int j = 0; j < 6; ++j)
        BTCOMB(d[0][j], d[1][j], d[2][j], d[3][j], d[4][j], d[5][j],
               e[0][j], e[1][j], e[2][j], e[3][j], e[4][j], e[5][j]);

    size_t base = (size_t)img * VIMG + (size_t)(c4 * 4 + c) * 4096 +
                  ty * 64 + tx;
#pragma unroll
    for (int i = 0; i < 6; ++i) {
        float o[6];
        BTCOMB(e[i][0], e[i][1], e[i][2], e[i][3], e[i][4], e[i][5],
               o[0], o[1], o[2], o[3], o[4], o[5]);
#pragma unroll
        for (int j = 0; j < 6; ++j) {
            size_t off = base + (size_t)(i * 6 + j) * 524288;
            __nv_bfloat16 h, l;
            bf16_split(o[j], h, l);
            vh[off] = h; vl[off] = l;
        }
    }
}

// FF-stage input transform (2 images from gQ)
__global__ __launch_bounds__(256) void wino_in(
    const float* __restrict__ x, __nv_bfloat16* __restrict__ vh)
{
    __nv_bfloat16* vl = vh + 14ull * VIMG;
    __shared__ __align__(16) float s_d[4][6][264];
    int img = blockIdx.z, ty = blockIdx.y, c4 = blockIdx.x;
    int tid = threadIdx.x;
    const float* xb = x + (size_t)img * IMG + (size_t)(c4 * 4) * HWSZ;

    for (int i = tid; i < 4 * 6 * 258; i += 256) {
        int c = i / (6 * 258);
        int rem = i - c * (6 * 258);
        int r = rem / 258, col = rem - r * 258;
        int gy = ty * 4 - 1 + r, gx = col - 1;
        float v = 0.f;
        if ((unsigned)gy < 256u && (unsigned)gx < 256u)
            v = xb[(size_t)c * HWSZ + gy * 256 + gx];
        s_d[c][r][col] = v;
    }
    __syncthreads();

    int tx = tid & 63, c = tid >> 6;
    float d[6][6];
#pragma unroll
    for (int r = 0; r < 6; ++r) {
        const float4* row = (const float4*)s_d[c][r];
        float4 a = row[tx], b = row[tx + 1];
        d[r][0] = a.x; d[r][1] = a.y; d[r][2] = a.z;
        d[r][3] = a.w; d[r][4] = b.x; d[r][5] = b.y;
    }
    float e[6][6];
#pragma unroll
    for (int j = 0; j < 6; ++j)
        BTCOMB(d[0][j], d[1][j], d[2][j], d[3][j], d[4][j], d[5][j],
               e[0][j], e[1][j], e[2][j], e[3][j], e[4][j], e[5][j]);

    size_t base = (size_t)img * VIMG + (size_t)(c4 * 4 + c) * 4096 +
                  ty * 64 + tx;
#pragma unroll
    for (int i = 0; i < 6; ++i) {
        float o[6];
        BTCOMB(e[i][0], e[i][1], e[i][2], e[i][3], e[i][4], e[i][5],
               o[0], o[1], o[2], o[3], o[4], o[5]);
#pragma unroll
        for (int j = 0; j < 6; ++j) {
            size_t off = base + (size_t)(i * 6 + j) * 524288;
            __nv_bfloat16 h, l;
            bf16_split(o[j], h, l);
            vh[off] = h; vl[off] = l;
        }
    }
}

// ---------------------------------------------------------------------------
// Winograd GEMM v4 (HMMA): block = 128 oc x 64 tiles, 256 threads,
// 2 CTAs/SM (58 KB smem, <=128 regs via spill-safe B-frag loads).
// Warp (8 = 2m x 4n): 64 oc x 16 tiles. K = 128 ic, cp.async 2-stage.
// smem: As 2 st x (2 term x 128 rows x 80B) = 40960
//       Bs 2 st x (2 term x 32 rows x 144B) = 18432  -> 59392 total
// ---------------------------------------------------------------------------
#define GEMM_SMEM 59392
#define AS_STAGE 20480
#define AS_TERM  10240
#define BS_BASE  40960
#define BS_STAGE 9216
#define BS_TERM  4608

__global__ __launch_bounds__(256, 2) void wino_gemm_mma(
    const __nv_bfloat16* __restrict__ vh, const __nv_bfloat16* __restrict__ uh,
    float* __restrict__ mout, int route)
{
    extern __shared__ __align__(16) char smx[];
    const __nv_bfloat16* vl = vh + 14ull * VIMG;
    const __nv_bfloat16* ul = uh + 3ull * 36 * 16384;

    int pos = blockIdx.y, img = blockIdx.z, tb = blockIdx.x;
    int tid = threadIdx.x, l = tid & 31, wid = tid >> 5;
    int warp_m = wid & 1, warp_n = wid >> 1;

    int uset = route ? ((img < 2) ? 0 : 1) : 2;
    size_t uoff = (size_t)uset * (36 * 16384) + (size_t)pos * 16384;
    size_t voff = (size_t)img * VIMG + (size_t)pos * 524288 + tb * 64;

    uint32_t sb = smem_u32(smx);

#define COPY_CHUNK(chunk, buf) do {                                         \
    int _ic0 = (chunk) * 32;                                                \
    _Pragma("unroll")                                                       \
    for (int _i = 0; _i < 4; ++_i) {                                        \
        int _t = tid + _i * 256;                                            \
        int _term = _t >> 9, _r = (_t >> 2) & 127, _s = _t & 3;             \
        const __nv_bfloat16* _src =                                         \
            (_term ? ul : uh) + uoff + _r * 128 + _ic0 + _s * 8;            \
        cp16(sb + (buf) * AS_STAGE + _term * AS_TERM + _r * 80 + _s * 16,   \
             _src);                                                         \
    }                                                                       \
    _Pragma("unroll")                                                       \
    for (int _i = 0; _i < 2; ++_i) {                                        \
        int _j = tid + _i * 256;                                            \
        int _bt = _j >> 8, _br = (_j >> 3) & 31, _bs = _j & 7;              \
        const __nv_bfloat16* _bsrc =                                        \
            (_bt ? vl : vh) + voff + (size_t)(_ic0 + _br) * 4096 + _bs * 8; \
        cp16(sb + BS_BASE + (buf) * BS_STAGE + _bt * BS_TERM +              \
             _br * 144 + _bs * 16, _bsrc);                                  \
    }                                                                       \
    CP_COMMIT();                                                            \
} while (0)

    float d[4][2][4];
#pragma unroll
    for (int mt = 0; mt < 4; ++mt)
#pragma unroll
        for (int nt = 0; nt < 2; ++nt)
#pragma unroll
            for (int k = 0; k < 4; ++k) d[mt][nt][k] = 0.f;

    COPY_CHUNK(0, 0);

    for (int c = 0; c < 4; ++c) {
        int buf = c & 1;
        if (c < 3) {
            COPY_CHUNK(c + 1, buf ^ 1);
            CP_WAIT(1);
        } else {
            CP_WAIT(0);
        }
        __syncthreads();

#pragma unroll
        for (int ks = 0; ks < 2; ++ks) {
            uint32_t ah[4][4], al[4][4];
#pragma unroll
            for (int mt = 0; mt < 4; ++mt) {
                uint32_t aa = sb + buf * AS_STAGE +
                    (warp_m * 64 + mt * 16 + (l & 15)) * 80 +
                    ks * 32 + (l >> 4) * 16;
                ldsm4(ah[mt], aa);
                ldsm4(al[mt], aa + AS_TERM);
            }
            // single 16-col B group per warp; hi/lo loaded back-to-back
            uint32_t bh[4], bl[4];
            uint32_t ba = sb + BS_BASE + buf * BS_STAGE +
                          (ks * 16 + (l & 15)) * 144 +
                          warp_n * 32 + (l >> 4) * 16;
            ldsm4t(bh, ba);
            ldsm4t(bl, ba + BS_TERM);
#pragma unroll
            for (int mt = 0; mt < 4; ++mt) {
                float* d0 = d[mt][0];
                float* d1 = d[mt][1];
                mma_bf16(d0, ah[mt], bh[0], bh[1]);
                mma_bf16(d1, ah[mt], bh[2], bh[3]);
                mma_bf16(d0, al[mt], bh[0], bh[1]);
                mma_bf16(d1, al[mt], bh[2], bh[3]);
                mma_bf16(d0, ah[mt], bl[0], bl[1]);
                mma_bf16(d1, ah[mt], bl[2], bl[3]);
            }
        }
        __syncthreads();
    }

    float* Mo = mout + (size_t)img * VIMG + (size_t)pos * 524288 + tb * 64;
#pragma unroll
    for (int mt = 0; mt < 4; ++mt)
#pragma unroll
        for (int nt = 0; nt < 2; ++nt) {
            int oc0 = warp_m * 64 + mt * 16 + (l >> 2);
            int t0  = warp_n * 16 + nt * 8 + (l & 3) * 2;
            float2 v01 = make_float2(d[mt][nt][0], d[mt][nt][1]);
            float2 v23 = make_float2(d[mt][nt][2], d[mt][nt][3]);
            *(float2*)(Mo + (size_t)oc0 * 4096 + t0) = v01;
            *(float2*)(Mo + (size_t)(oc0 + 8) * 4096 + t0) = v23;
        }
#undef COPY_CHUNK
}

// ---------------------------------------------------------------------------
// Merged output transform + bias + PReLU + residual, per-image routing.
// ---------------------------------------------------------------------------
__global__ __launch_bounds__(256) void wino_out14(
    const float* __restrict__ mout,
    const float* __restrict__ r0, const float* __restrict__ r1,
    const float* __restrict__ r2,
    float* __restrict__ y0, float* __restrict__ y1, float* __restrict__ y2,
    const float* __restrict__ bias0, const float* __restrict__ alpha0,
    const float* __restrict__ bias1, const float* __restrict__ alpha1,
    int route)
{
    __shared__ __align__(16) float s_o[8][4][256];
    int img = blockIdx.z, ty = blockIdx.y, og = blockIdx.x;
    int tid = threadIdx.x;

    const float* resid; float* y; const float* bias; const float* alpha;
    if (!route || img < 2) {
        resid = r0 + (size_t)img * IMG; y = y0 + (size_t)img * IMG;
        bias = bias0; alpha = alpha0;
    } else if (img < 6) {
        resid = r1 + (size_t)(img - 2) * IMG; y = y1 + (size_t)(img - 2) * IMG;
        bias = bias1; alpha = alpha1;
    } else {
        resid = r2 + (size_t)(img - 6) * IMG; y = y2 + (size_t)(img - 6) * IMG;
        bias = bias1; alpha = alpha1;
    }

#pragma unroll
    for (int it = 0; it < 2; ++it) {
        int item = tid + it * 256;
        int tx = item & 63, ol = item >> 6;
        const float* Mp = mout + (size_t)img * VIMG +
                          (size_t)(og * 8 + ol) * 4096 + ty * 64 + tx;
        float m[6][6];
#pragma unroll
        for (int pos = 0; pos < 36; ++pos)
            m[pos / 6][pos % 6] = Mp[(size_t)pos * 524288];
        float e[4][6];
#pragma unroll
        for (int j = 0; j < 6; ++j)
            ATCOMB(m[0][j], m[1][j], m[2][j], m[3][j], m[4][j], m[5][j],
                   e[0][j], e[1][j], e[2][j], e[3][j]);
#pragma unroll
        for (int r = 0; r < 4; ++r) {
            float o0, o1, o2, o3;
            ATCOMB(e[r][0], e[r][1], e[r][2], e[r][3], e[r][4], e[r][5],
                   o0, o1, o2, o3);
            ((float4*)s_o[ol][r])[tx] = make_float4(o0, o1, o2, o3);
        }
    }
    __syncthreads();

    float a = alpha[0];
    for (int i = tid; i < 8192; i += 256) {
        int ol = i >> 10, rem = i & 1023, r = rem >> 8, px = rem & 255;
        int oc = og * 8 + ol;
        int gy = ty * 4 + r;
        size_t addr = (size_t)oc * HWSZ + gy * 256 + px;
        float v = s_o[ol][r][px] + bias[oc];
        v = (v >= 0.f) ? v : a * v;
        y[addr] = resid[addr] + v;
    }
}

// ---------------------------------------------------------------------------
// Windowed dual-branch attention v5 (R13 passing version)
// ---------------------------------------------------------------------------
#define SST 392
#define PST 66
#define VDST 129
#define OST 66
#define OFF_P 25088
#define OFF_SM 50432
#define ATTN_SMEM 201984
#define NK 384

__global__ __launch_bounds__(256, 1) void win_attn(
    float* __restrict__ Qbuf, const float* __restrict__ KV,
    const float* __restrict__ KVw, const float* __restrict__ em)
{
    extern __shared__ __align__(16) float sm[];
    __nv_bfloat16* qbf = (__nv_bfloat16*)sm;
    __nv_bfloat16* kbf = (__nv_bfloat16*)sm + 17408;
    float* s_s = sm;
    float* s_p = sm + OFF_P;
    unsigned long long* s_v2 = (unsigned long long*)sm;
    float* s_m = sm + OFF_SM;

    int bwin = blockIdx.x;
    int bb  = bwin >> 10;
    int wy8 = ((bwin >> 5) & 31) << 3;
    int wx8 = (bwin & 31) << 3;
    int tid = threadIdx.x;
    int l = tid & 31, wid = tid >> 5;
    int warp_m = wid & 1, warp_n = wid >> 1;
    uint32_t sb = smem_u32(sm);

    float* qimg = Qbuf + (size_t)bb * IMG;
    const float* kv0 = KV + (size_t)bb * 2 * IMG;
    const float* kv1 = KVw + (size_t)bb * 4 * IMG;

    for (int i = tid; i < 64 * CC; i += 256) {
        int q = i & 63, c = i >> 6;
        int gy = wy8 + (q >> 3), gx = wx8 + (q & 7);
        float v = qimg[(size_t)c * HWSZ + gy * WW + gx];
        __nv_bfloat16 h, lo;
        bf16_split(v, h, lo);
        qbf[q * 136 + c] = h;
        qbf[8704 + q * 136 + c] = lo;
    }
    if (tid < 64) {
        int gy = wy8 + (tid >> 3), gx = wx8 + (tid & 7);
        s_m[tid] = em[(size_t)bb * HWSZ + gy * WW + gx];
    }

    float d[2][12][4];
#pragma unroll
    for (int mt = 0; mt < 2; ++mt)
#pragma unroll
        for (int nt = 0; nt < 12; ++nt)
#pragma unroll
            for (int x = 0; x < 4; ++x) d[mt][nt][x] = 0.f;

    for (int chunk = 0; chunk < 2; ++chunk) {
        __syncthreads();
        for (int i = tid; i < 64 * NK; i += 256) {
            int k = i % NK, c2 = i / NK;
            int c = chunk * 64 + c2;
            const float* base;
            int t;
            if (k < 128) { base = kv0 + (size_t)(k >> 6) * IMG; t = k & 63; }
            else { int kk = k - 128; base = kv1 + (size_t)(kk >> 6) * IMG; t = kk & 63; }
            int gy = wy8 + (t >> 3), gx = wx8 + (t & 7);
            float v = base[(size_t)c * HWSZ + gy * WW + gx];
            __nv_bfloat16 h, lo;
            bf16_split(v, h, lo);
            kbf[c2 * 392 + k] = h;
            kbf[25088 + c2 * 392 + k] = lo;
        }
        __syncthreads();

#pragma unroll
        for (int kc = 0; kc < 4; ++kc) {
            uint32_t ah[2][4], al[2][4];
#pragma unroll
            for (int mt = 0; mt < 2; ++mt) {
                uint32_t aa = sb + (warp_m * 32 + mt * 16 + (l & 15)) * 272 +
                              chunk * 128 + kc * 32 + (l >> 4) * 16;
                ldsm4(ah[mt], aa);
                ldsm4(al[mt], aa + 17408);
            }
#pragma unroll
            for (int n2 = 0; n2 < 6; ++n2) {
                uint32_t bh[4], bl[4];
                uint32_t ba = sb + 34816 + (kc * 16 + (l & 15)) * 784 +
                              (warp_n * 96 + n2 * 16) * 2 + (l >> 4) * 16;
                ldsm4t(bh, ba);
                ldsm4t(bl, ba + 50176);
#pragma unroll
                for (int mt = 0; mt < 2; ++mt) {
                    float* d0 = d[mt][n2 * 2];
                    float* d1 = d[mt][n2 * 2 + 1];
                    mma_bf16(d0, ah[mt], bh[0], bh[1]);
                    mma_bf16(d1, ah[mt], bh[2], bh[3]);
                    mma_bf16(d0, al[mt], bh[0], bh[1]);
                    mma_bf16(d1, al[mt], bh[2], bh[3]);
                    mma_bf16(d0, ah[mt], bl[0], bl[1]);
                    mma_bf16(d1, ah[mt], bl[2], bl[3]);
                }
            }
        }
    }

    __syncthreads();
#pragma unroll
    for (int mt = 0; mt < 2; ++mt)
#pragma unroll
        for (int nt = 0; nt < 12; ++nt) {
            int r0 = warp_m * 32 + mt * 16 + (l >> 2);
            int c0 = warp_n * 96 + nt * 8 + (l & 3) * 2;
            *(float2*)(s_s + (size_t)r0 * SST + c0) =
                make_float2(d[mt][nt][0], d[mt][nt][1]);
            *(float2*)(s_s + (size_t)(r0 + 8) * SST + c0) =
                make_float2(d[mt][nt][2], d[mt][nt][3]);
        }
    __syncthreads();

    const float SCALE = 0.08838834764831845f;
    if (tid < 128) {
        int r = tid & 63, br = tid >> 6;
        float* row = s_s + (size_t)r * SST;
        float msk = s_m[r];
        int k0 = br ? 128 : 0, k1 = br ? 384 : 128;
        float m0 = -3.4e38f, m1 = -3.4e38f;
        for (int k = k0; k < k1; k += 2) {
            m0 = fmaxf(m0, row[k]);
            m1 = fmaxf(m1, row[k + 1]);
        }
        float m = fmaxf(m0, m1) * SCALE;
        float s0 = 0.f, s1 = 0.f;
        for (int k = k0; k < k1; k += 2) {
            float e0 = __expf(row[k] * SCALE - m);
            float e1 = __expf(row[k + 1] * SCALE - m);
            row[k] = e0; row[k + 1] = e1;
            s0 += e0; s1 += e1;
        }
        float wgt = br ? (1.f - msk) : msk;
        float inv = wgt / (s0 + s1);
        for (int k = k0; k < k1; ++k)
            s_p[(size_t)k * PST + r] = row[k] * inv;
    }

    int qb = wid, kidx = l;
    unsigned long long oacc[4][4];
#pragma unroll
    for (int p = 0; p < 4; ++p)
#pragma unroll
        for (int jc = 0; jc < 4; ++jc) oacc[p][jc] = 0ull;

    for (int kc = 0; kc < 6; ++kc) {
        __syncthreads();
        for (int i = tid; i < 64 * CC; i += 256) {
            int kk = i & 63, c = i >> 6;
            int k = kc * 64 + kk;
            const float* base;
            if (k < 128) base = kv0 + (size_t)(k >> 6) * IMG;
            else         base = kv1 + (size_t)((k - 128) >> 6) * IMG;
            int gy = wy8 + (kk >> 3), gx = wx8 + (kk & 7);
            float vv = base[(size_t)c * HWSZ + gy * WW + gx];
            s_v2[kk * VDST + c] = pack2(vv, vv);
        }
        __syncthreads();

#pragma unroll 2
        for (int kk = 0; kk < 64; ++kk) {
            int k = kc * 64 + kk;
            const unsigned long long* pp =
                (const unsigned long long*)(s_p + (size_t)k * PST + qb * 8);
            unsigned long long p0 = pp[0], p1 = pp[1], p2 = pp[2], p3 = pp[3];
            const unsigned long long* vrow = s_v2 + kk * VDST + kidx;
#pragma unroll
            for (int jc = 0; jc < 4; ++jc) {
                unsigned long long v2 = vrow[32 * jc];
                ffma2(oacc[0][jc], p0, v2);
                ffma2(oacc[1][jc], p1, v2);
                ffma2(oacc[2][jc], p2, v2);
                ffma2(oacc[3][jc], p3, v2);
            }
        }
    }

    __syncthreads();
    float* s_o = sm;
#pragma unroll
    for (int jc = 0; jc < 4; ++jc) {
        int c = kidx + 32 * jc;
#pragma unroll
        for (int p = 0; p < 4; ++p)
            *(unsigned long long*)(s_o + c * OST + qb * 8 + 2 * p) = oacc[p][jc];
    }
    __syncthreads();
    for (int i = tid; i < 64 * CC; i += 256) {
        int q = i & 63, c = i >> 6;
        int gy = wy8 + (q >> 3), gx = wx8 + (q & 7);
        qimg[(size_t)c * HWSZ + gy * WW + gx] += s_o[c * OST + q];
    }
}

// ---------------------------------------------------------------------------
extern "C" void kernel_launch(void* const* d_in, const int* in_sizes, int n_in,
                              void* d_out, int out_size)
{
    const float* xq   = (const float*)d_in[0];
    const float* xkvw = (const float*)d_in[1];
    const float* xkv  = (const float*)d_in[2];
    const float* em   = (const float*)d_in[3];
    const float* Wq   = (const float*)d_in[4];
    const float* bq   = (const float*)d_in[5];
    const float* aq   = (const float*)d_in[6];
    const float* Wkv  = (const float*)d_in[7];
    const float* bkv  = (const float*)d_in[8];
    const float* akv  = (const float*)d_in[9];
    const float* Wff  = (const float*)d_in[10];
    const float* bff  = (const float*)d_in[11];
    const float* aff  = (const float*)d_in[12];
    float* out = (float*)d_out;

    float *gQ = nullptr, *gKV = nullptr, *gKVw = nullptr;
    float *gV = nullptr, *gM = nullptr, *gU = nullptr;
    cudaGetSymbolAddress((void**)&gQ,   g_Q);
    cudaGetSymbolAddress((void**)&gKV,  g_KV);
    cudaGetSymbolAddress((void**)&gKVw, g_KVw);
    cudaGetSymbolAddress((void**)&gV,   g_V);
    cudaGetSymbolAddress((void**)&gM,   g_M);
    cudaGetSymbolAddress((void**)&gU,   g_U);

    __nv_bfloat16* gVh = (__nv_bfloat16*)gV;
    __nv_bfloat16* gUh = (__nv_bfloat16*)gU;

    cudaFuncSetAttribute(win_attn, cudaFuncAttributeMaxDynamicSharedMemorySize,
                         ATTN_SMEM);
    cudaFuncSetAttribute(wino_gemm_mma,
                         cudaFuncAttributeMaxDynamicSharedMemorySize, GEMM_SMEM);

    dim3 blk(256);

    wino_filt3<<<192, blk>>>(Wq, Wkv, Wff, gUh);

    wino_in14<<<dim3(32, 64, 14), blk>>>(xq, xkv, xkvw, gVh);
    wino_gemm_mma<<<dim3(64, 36, 14), blk, GEMM_SMEM>>>(gVh, gUh, gM, 1);
    wino_out14<<<dim3(16, 64, 14), blk>>>(gM, xq, xkv, xkvw, gQ, gKV, gKVw,
                                          bq, aq, bkv, akv, 1);

    win_attn<<<2048, blk, ATTN_SMEM>>>(gQ, gKV, gKVw, em);

    wino_in<<<dim3(32, 64, 2), blk>>>(gQ, gVh);
    wino_gemm_mma<<<dim3(64, 36, 2), blk, GEMM_SMEM>>>(gVh, gUh, gM, 0);
    wino_out14<<<dim3(16, 64, 2), blk>>>(gM, gQ, gQ, gQ, out, out, out,
                                         bff, aff, bff, aff, 0);
}

// round 15
// speedup vs baseline: 1.3732x; 1.0343x over previous
#include <cuda_runtime.h>
#include <cuda_bf16.h>
#include <cstdint>

#define HH 256
#define WW 256
#define CC 128
#define HWSZ 65536
#define IMG (CC * HH * WW)
#define VIMG (36ull * 128 * 4096)

// ---------------- scratch ----------------------------------------------------
__device__ float g_Q[2ull * IMG];
__device__ float g_KV[4ull * IMG];
__device__ float g_KVw[8ull * IMG];
__device__ float g_V[14ull * VIMG];
__device__ float g_M[14ull * VIMG];
__device__ float g_U[3ull * 36 * 128 * 128];

// ---------------- helpers ----------------------------------------------------
__device__ __forceinline__ void cp16(uint32_t saddr, const void* g) {
    asm volatile("cp.async.cg.shared.global [%0], [%1], 16;"
                 :: "r"(saddr), "l"(g) : "memory");
}
#define CP_COMMIT() asm volatile("cp.async.commit_group;" ::: "memory")
#define CP_WAIT(n)  asm volatile("cp.async.wait_group %0;" :: "n"(n) : "memory")

__device__ __forceinline__ uint32_t smem_u32(const void* p) {
    uint32_t a;
    asm("{ .reg .u64 t; cvta.to.shared.u64 t, %1; cvt.u32.u64 %0, t; }"
        : "=r"(a) : "l"(p));
    return a;
}
__device__ __forceinline__ void ldsm4(uint32_t* r, uint32_t a) {
    asm volatile("ldmatrix.sync.aligned.m8n8.x4.shared.b16 {%0,%1,%2,%3}, [%4];"
        : "=r"(r[0]), "=r"(r[1]), "=r"(r[2]), "=r"(r[3]) : "r"(a));
}
__device__ __forceinline__ void ldsm4t(uint32_t* r, uint32_t a) {
    asm volatile("ldmatrix.sync.aligned.m8n8.x4.trans.shared.b16 {%0,%1,%2,%3}, [%4];"
        : "=r"(r[0]), "=r"(r[1]), "=r"(r[2]), "=r"(r[3]) : "r"(a));
}
__device__ __forceinline__ void mma_bf16(float* d, const uint32_t* a,
                                         uint32_t b0, uint32_t b1) {
    asm volatile(
        "mma.sync.aligned.m16n8k16.row.col.f32.bf16.bf16.f32 "
        "{%0,%1,%2,%3}, {%4,%5,%6,%7}, {%8,%9}, {%0,%1,%2,%3};"
        : "+f"(d[0]), "+f"(d[1]), "+f"(d[2]), "+f"(d[3])
        : "r"(a[0]), "r"(a[1]), "r"(a[2]), "r"(a[3]), "r"(b0), "r"(b1));
}

#define BTCOMB(d0,d1,d2,d3,d4,d5,o0,o1,o2,o3,o4,o5) do {                   \
    o0 = 4.f*(d0) - 5.f*(d2) + (d4);                                       \
    float _a = (d4) - 4.f*(d2), _b = (d3) - 4.f*(d1);                      \
    o1 = _a + _b; o2 = _a - _b;                                            \
    float _c = (d4) - (d2), _e = 2.f*((d3) - (d1));                        \
    o3 = _c + _e; o4 = _c - _e;                                            \
    o5 = 4.f*(d1) - 5.f*(d3) + (d5);                                       \
} while (0)

#define ATCOMB(m0,m1,m2,m3,m4,m5,o0,o1,o2,o3) do {                         \
    float _s = (m1)+(m2), _d = (m1)-(m2), _t = (m3)+(m4), _u = (m3)-(m4);  \
    o0 = (m0) + _s + _t;                                                   \
    o1 = _d + 2.f*_u;                                                      \
    o2 = _s + 4.f*_t;                                                      \
    o3 = _d + 8.f*_u + (m5);                                               \
} while (0)

#define GCOMB(w0,w1,w2,o0,o1,o2,o3,o4,o5) do {                             \
    o0 = 0.25f*(w0);                                                       \
    float _n = -(w0) - (w2);                                               \
    o1 = (_n - (w1)) * (1.f/6.f);                                          \
    o2 = (_n + (w1)) * (1.f/6.f);                                          \
    float _p = (w0)*(1.f/24.f) + (w2)*(1.f/6.f), _q = (w1)*(1.f/12.f);     \
    o3 = _p + _q; o4 = _p - _q;                                            \
    o5 = (w2);                                                             \
} while (0)

__device__ __forceinline__ void bf16_split(float v, __nv_bfloat16& h,
                                           __nv_bfloat16& l) {
    h = __float2bfloat16(v);
    l = __float2bfloat16(v - __bfloat162float(h));
}

// ---------------------------------------------------------------------------
// Filter transform -> bf16 hi/lo planes, layout [set][pos][oc][ic]
// ---------------------------------------------------------------------------
__global__ __launch_bounds__(256) void wino_filt3(
    const float* __restrict__ W0, const float* __restrict__ W1,
    const float* __restrict__ W2, __nv_bfloat16* __restrict__ Uh)
{
    __nv_bfloat16* Ul = Uh + 3ull * 36 * 16384;
    int idx = blockIdx.x * 256 + threadIdx.x;
    if (idx >= 3 * 16384) return;
    int set = idx >> 14, e = idx & 16383;
    int oc = e & 127, ic = e >> 7;
    const float* W = (set == 0) ? W0 : (set == 1) ? W1 : W2;
    size_t soff = (size_t)set * (36 * 16384);
    float w[3][3];
#pragma unroll
    for (int a = 0; a < 3; ++a)
#pragma unroll
        for (int b = 0; b < 3; ++b)
            w[a][b] = W[(size_t)oc * 1152 + ic * 9 + a * 3 + b];
    float ee[6][3];
#pragma unroll
    for (int b = 0; b < 3; ++b)
        GCOMB(w[0][b], w[1][b], w[2][b],
              ee[0][b], ee[1][b], ee[2][b], ee[3][b], ee[4][b], ee[5][b]);
#pragma unroll
    for (int i = 0; i < 6; ++i) {
        float u[6];
        GCOMB(ee[i][0], ee[i][1], ee[i][2], u[0], u[1], u[2], u[3], u[4], u[5]);
#pragma unroll
        for (int j = 0; j < 6; ++j) {
            size_t off = soff + (size_t)(i * 6 + j) * 16384 + oc * 128 + ic;
            __nv_bfloat16 h, l;
            bf16_split(u[j], h, l);
            Uh[off] = h; Ul[off] = l;
        }
    }
}

// ---------------------------------------------------------------------------
// Merged input transform -> bf16 hi/lo V planes [img][pos][ic][tile]
// ---------------------------------------------------------------------------
__global__ __launch_bounds__(256) void wino_in14(
    const float* __restrict__ xq, const float* __restrict__ xkv,
    const float* __restrict__ xkvw, __nv_bfloat16* __restrict__ vh)
{
    __nv_bfloat16* vl = vh + 14ull * VIMG;
    __shared__ __align__(16) float s_d[4][6][264];
    int img = blockIdx.z, ty = blockIdx.y, c4 = blockIdx.x;
    int tid = threadIdx.x;
    const float* xb;
    if (img < 2)      xb = xq   + (size_t)img * IMG;
    else if (img < 6) xb = xkv  + (size_t)(img - 2) * IMG;
    else              xb = xkvw + (size_t)(img - 6) * IMG;
    xb += (size_t)(c4 * 4) * HWSZ;

    for (int i = tid; i < 4 * 6 * 258; i += 256) {
        int c = i / (6 * 258);
        int rem = i - c * (6 * 258);
        int r = rem / 258, col = rem - r * 258;
        int gy = ty * 4 - 1 + r, gx = col - 1;
        float v = 0.f;
        if ((unsigned)gy < 256u && (unsigned)gx < 256u)
            v = xb[(size_t)c * HWSZ + gy * 256 + gx];
        s_d[c][r][col] = v;
    }
    __syncthreads();

    int tx = tid & 63, c = tid >> 6;
    float d[6][6];
#pragma unroll
    for (int r = 0; r < 6; ++r) {
        const float4* row = (const float4*)s_d[c][r];
        float4 a = row[tx], b = row[tx + 1];
        d[r][0] = a.x; d[r][1] = a.y; d[r][2] = a.z;
        d[r][3] = a.w; d[r][4] = b.x; d[r][5] = b.y;
    }
    float e[6][6];
#pragma unroll
    for (int j = 0; j < 6; ++j)
        BTCOMB(d[0][j], d[1][j], d[2][j], d[3][j], d[4][j], d[5][j],
               e[0][j], e[1][j], e[2][j], e[3][j], e[4][j], e[5][j]);

    size_t base = (size_t)img * VIMG + (size_t)(c4 * 4 + c) * 4096 +
                  ty * 64 + tx;
#pragma unroll
    for (int i = 0; i < 6; ++i) {
        float o[6];
        BTCOMB(e[i][0], e[i][1], e[i][2], e[i][3], e[i][4], e[i][5],
               o[0], o[1], o[2], o[3], o[4], o[5]);
#pragma unroll
        for (int j = 0; j < 6; ++j) {
            size_t off = base + (size_t)(i * 6 + j) * 524288;
            __nv_bfloat16 h, l;
            bf16_split(o[j], h, l);
            vh[off] = h; vl[off] = l;
        }
    }
}

// FF-stage input transform (2 images from gQ)
__global__ __launch_bounds__(256) void wino_in(
    const float* __restrict__ x, __nv_bfloat16* __restrict__ vh)
{
    __nv_bfloat16* vl = vh + 14ull * VIMG;
    __shared__ __align__(16) float s_d[4][6][264];
    int img = blockIdx.z, ty = blockIdx.y, c4 = blockIdx.x;
    int tid = threadIdx.x;
    const float* xb = x + (size_t)img * IMG + (size_t)(c4 * 4) * HWSZ;

    for (int i = tid; i < 4 * 6 * 258; i += 256) {
        int c = i / (6 * 258);
        int rem = i - c * (6 * 258);
        int r = rem / 258, col = rem - r * 258;
        int gy = ty * 4 - 1 + r, gx = col - 1;
        float v = 0.f;
        if ((unsigned)gy < 256u && (unsigned)gx < 256u)
            v = xb[(size_t)c * HWSZ + gy * 256 + gx];
        s_d[c][r][col] = v;
    }
    __syncthreads();

    int tx = tid & 63, c = tid >> 6;
    float d[6][6];
#pragma unroll
    for (int r = 0; r < 6; ++r) {
        const float4* row = (const float4*)s_d[c][r];
        float4 a = row[tx], b = row[tx + 1];
        d[r][0] = a.x; d[r][1] = a.y; d[r][2] = a.z;
        d[r][3] = a.w; d[r][4] = b.x; d[r][5] = b.y;
    }
    float e[6][6];
#pragma unroll
    for (int j = 0; j < 6; ++j)
        BTCOMB(d[0][j], d[1][j], d[2][j], d[3][j], d[4][j], d[5][j],
               e[0][j], e[1][j], e[2][j], e[3][j], e[4][j], e[5][j]);

    size_t base = (size_t)img * VIMG + (size_t)(c4 * 4 + c) * 4096 +
                  ty * 64 + tx;
#pragma unroll
    for (int i = 0; i < 6; ++i) {
        float o[6];
        BTCOMB(e[i][0], e[i][1], e[i][2], e[i][3], e[i][4], e[i][5],
               o[0], o[1], o[2], o[3], o[4], o[5]);
#pragma unroll
        for (int j = 0; j < 6; ++j) {
            size_t off = base + (size_t)(i * 6 + j) * 524288;
            __nv_bfloat16 h, l;
            bf16_split(o[j], h, l);
            vh[off] = h; vl[off] = l;
        }
    }
}

// ---------------------------------------------------------------------------
// Winograd GEMM v4 (HMMA, R14 passing version)
// ---------------------------------------------------------------------------
#define GEMM_SMEM 59392
#define AS_STAGE 20480
#define AS_TERM  10240
#define BS_BASE  40960
#define BS_STAGE 9216
#define BS_TERM  4608

__global__ __launch_bounds__(256, 2) void wino_gemm_mma(
    const __nv_bfloat16* __restrict__ vh, const __nv_bfloat16* __restrict__ uh,
    float* __restrict__ mout, int route)
{
    extern __shared__ __align__(16) char smx[];
    const __nv_bfloat16* vl = vh + 14ull * VIMG;
    const __nv_bfloat16* ul = uh + 3ull * 36 * 16384;

    int pos = blockIdx.y, img = blockIdx.z, tb = blockIdx.x;
    int tid = threadIdx.x, l = tid & 31, wid = tid >> 5;
    int warp_m = wid & 1, warp_n = wid >> 1;

    int uset = route ? ((img < 2) ? 0 : 1) : 2;
    size_t uoff = (size_t)uset * (36 * 16384) + (size_t)pos * 16384;
    size_t voff = (size_t)img * VIMG + (size_t)pos * 524288 + tb * 64;

    uint32_t sb = smem_u32(smx);

#define COPY_CHUNK(chunk, buf) do {                                         \
    int _ic0 = (chunk) * 32;                                                \
    _Pragma("unroll")                                                       \
    for (int _i = 0; _i < 4; ++_i) {                                        \
        int _t = tid + _i * 256;                                            \
        int _term = _t >> 9, _r = (_t >> 2) & 127, _s = _t & 3;             \
        const __nv_bfloat16* _src =                                         \
            (_term ? ul : uh) + uoff + _r * 128 + _ic0 + _s * 8;            \
        cp16(sb + (buf) * AS_STAGE + _term * AS_TERM + _r * 80 + _s * 16,   \
             _src);                                                         \
    }                                                                       \
    _Pragma("unroll")                                                       \
    for (int _i = 0; _i < 2; ++_i) {                                        \
        int _j = tid + _i * 256;                                            \
        int _bt = _j >> 8, _br = (_j >> 3) & 31, _bs = _j & 7;              \
        const __nv_bfloat16* _bsrc =                                        \
            (_bt ? vl : vh) + voff + (size_t)(_ic0 + _br) * 4096 + _bs * 8; \
        cp16(sb + BS_BASE + (buf) * BS_STAGE + _bt * BS_TERM +              \
             _br * 144 + _bs * 16, _bsrc);                                  \
    }                                                                       \
    CP_COMMIT();                                                            \
} while (0)

    float d[4][2][4];
#pragma unroll
    for (int mt = 0; mt < 4; ++mt)
#pragma unroll
        for (int nt = 0; nt < 2; ++nt)
#pragma unroll
            for (int k = 0; k < 4; ++k) d[mt][nt][k] = 0.f;

    COPY_CHUNK(0, 0);

    for (int c = 0; c < 4; ++c) {
        int buf = c & 1;
        if (c < 3) {
            COPY_CHUNK(c + 1, buf ^ 1);
            CP_WAIT(1);
        } else {
            CP_WAIT(0);
        }
        __syncthreads();

#pragma unroll
        for (int ks = 0; ks < 2; ++ks) {
            uint32_t ah[4][4], al[4][4];
#pragma unroll
            for (int mt = 0; mt < 4; ++mt) {
                uint32_t aa = sb + buf * AS_STAGE +
                    (warp_m * 64 + mt * 16 + (l & 15)) * 80 +
                    ks * 32 + (l >> 4) * 16;
                ldsm4(ah[mt], aa);
                ldsm4(al[mt], aa + AS_TERM);
            }
            uint32_t bh[4], bl[4];
            uint32_t ba = sb + BS_BASE + buf * BS_STAGE +
                          (ks * 16 + (l & 15)) * 144 +
                          warp_n * 32 + (l >> 4) * 16;
            ldsm4t(bh, ba);
            ldsm4t(bl, ba + BS_TERM);
#pragma unroll
            for (int mt = 0; mt < 4; ++mt) {
                float* d0 = d[mt][0];
                float* d1 = d[mt][1];
                mma_bf16(d0, ah[mt], bh[0], bh[1]);
                mma_bf16(d1, ah[mt], bh[2], bh[3]);
                mma_bf16(d0, al[mt], bh[0], bh[1]);
                mma_bf16(d1, al[mt], bh[2], bh[3]);
                mma_bf16(d0, ah[mt], bl[0], bl[1]);
                mma_bf16(d1, ah[mt], bl[2], bl[3]);
            }
        }
        __syncthreads();
    }

    float* Mo = mout + (size_t)img * VIMG + (size_t)pos * 524288 + tb * 64;
#pragma unroll
    for (int mt = 0; mt < 4; ++mt)
#pragma unroll
        for (int nt = 0; nt < 2; ++nt) {
            int oc0 = warp_m * 64 + mt * 16 + (l >> 2);
            int t0  = warp_n * 16 + nt * 8 + (l & 3) * 2;
            float2 v01 = make_float2(d[mt][nt][0], d[mt][nt][1]);
            float2 v23 = make_float2(d[mt][nt][2], d[mt][nt][3]);
            *(float2*)(Mo + (size_t)oc0 * 4096 + t0) = v01;
            *(float2*)(Mo + (size_t)(oc0 + 8) * 4096 + t0) = v23;
        }
#undef COPY_CHUNK
}

// ---------------------------------------------------------------------------
// Merged output transform + bias + PReLU + residual, per-image routing.
// ---------------------------------------------------------------------------
__global__ __launch_bounds__(256) void wino_out14(
    const float* __restrict__ mout,
    const float* __restrict__ r0, const float* __restrict__ r1,
    const float* __restrict__ r2,
    float* __restrict__ y0, float* __restrict__ y1, float* __restrict__ y2,
    const float* __restrict__ bias0, const float* __restrict__ alpha0,
    const float* __restrict__ bias1, const float* __restrict__ alpha1,
    int route)
{
    __shared__ __align__(16) float s_o[8][4][256];
    int img = blockIdx.z, ty = blockIdx.y, og = blockIdx.x;
    int tid = threadIdx.x;

    const float* resid; float* y; const float* bias; const float* alpha;
    if (!route || img < 2) {
        resid = r0 + (size_t)img * IMG; y = y0 + (size_t)img * IMG;
        bias = bias0; alpha = alpha0;
    } else if (img < 6) {
        resid = r1 + (size_t)(img - 2) * IMG; y = y1 + (size_t)(img - 2) * IMG;
        bias = bias1; alpha = alpha1;
    } else {
        resid = r2 + (size_t)(img - 6) * IMG; y = y2 + (size_t)(img - 6) * IMG;
        bias = bias1; alpha = alpha1;
    }

#pragma unroll
    for (int it = 0; it < 2; ++it) {
        int item = tid + it * 256;
        int tx = item & 63, ol = item >> 6;
        const float* Mp = mout + (size_t)img * VIMG +
                          (size_t)(og * 8 + ol) * 4096 + ty * 64 + tx;
        float m[6][6];
#pragma unroll
        for (int pos = 0; pos < 36; ++pos)
            m[pos / 6][pos % 6] = Mp[(size_t)pos * 524288];
        float e[4][6];
#pragma unroll
        for (int j = 0; j < 6; ++j)
            ATCOMB(m[0][j], m[1][j], m[2][j], m[3][j], m[4][j], m[5][j],
                   e[0][j], e[1][j], e[2][j], e[3][j]);
#pragma unroll
        for (int r = 0; r < 4; ++r) {
            float o0, o1, o2, o3;
            ATCOMB(e[r][0], e[r][1], e[r][2], e[r][3], e[r][4], e[r][5],
                   o0, o1, o2, o3);
            ((float4*)s_o[ol][r])[tx] = make_float4(o0, o1, o2, o3);
        }
    }
    __syncthreads();

    float a = alpha[0];
    for (int i = tid; i < 8192; i += 256) {
        int ol = i >> 10, rem = i & 1023, r = rem >> 8, px = rem & 255;
        int oc = og * 8 + ol;
        int gy = ty * 4 + r;
        size_t addr = (size_t)oc * HWSZ + gy * 256 + px;
        float v = s_o[ol][r][px] + bias[oc];
        v = (v >= 0.f) ? v : a * v;
        y[addr] = resid[addr] + v;
    }
}

// ---------------------------------------------------------------------------
// Windowed dual-branch attention v6: QK + PV both via HMMA bf16 3-term.
// smem bytes:
//   QK phase: Qhi[0,17408) Qlo[17408,34816) Khi[34816,84992) Klo[84992,135168)
//   S fp32 [64][392] aliases [0,100352)
//   P bf16 hi [100352,150528), lo [150528,200704)  (rows 784B = 392 bf16)
//   PV phase: Vhi [0,34816) Vlo [34816,69632)  (rows 272B = 136 bf16)
//   O f32 [128][66] aliases [0,33792)
//   mask at [200704,200960)
// ---------------------------------------------------------------------------
#define SST 392
#define OST 66
#define ATTN_SMEM 200960
#define NK 384

__global__ __launch_bounds__(256, 1) void win_attn(
    float* __restrict__ Qbuf, const float* __restrict__ KV,
    const float* __restrict__ KVw, const float* __restrict__ em)
{
    extern __shared__ __align__(16) float sm[];
    __nv_bfloat16* qbf = (__nv_bfloat16*)sm;
    __nv_bfloat16* kbf = (__nv_bfloat16*)sm + 17408;
    float* s_s = sm;
    __nv_bfloat16* ph = (__nv_bfloat16*)((char*)sm + 100352);
    __nv_bfloat16* pl = ph + 25088;
    __nv_bfloat16* vbf = (__nv_bfloat16*)sm;
    float* s_m = (float*)((char*)sm + 200704);
    float* s_o = sm;

    int bwin = blockIdx.x;
    int bb  = bwin >> 10;
    int wy8 = ((bwin >> 5) & 31) << 3;
    int wx8 = (bwin & 31) << 3;
    int tid = threadIdx.x;
    int l = tid & 31, wid = tid >> 5;
    int warp_m = wid & 1, warp_n = wid >> 1;
    uint32_t sb = smem_u32(sm);

    float* qimg = Qbuf + (size_t)bb * IMG;
    const float* kv0 = KV + (size_t)bb * 2 * IMG;
    const float* kv1 = KVw + (size_t)bb * 4 * IMG;

    // ---- load Q as bf16 hi/lo [q][c] (272B rows)
    for (int i = tid; i < 64 * CC; i += 256) {
        int q = i & 63, c = i >> 6;
        int gy = wy8 + (q >> 3), gx = wx8 + (q & 7);
        float v = qimg[(size_t)c * HWSZ + gy * WW + gx];
        __nv_bfloat16 h, lo;
        bf16_split(v, h, lo);
        qbf[q * 136 + c] = h;
        qbf[8704 + q * 136 + c] = lo;
    }
    if (tid < 64) {
        int gy = wy8 + (tid >> 3), gx = wx8 + (tid & 7);
        s_m[tid] = em[(size_t)bb * HWSZ + gy * WW + gx];
    }

    // ================= QK via HMMA (R13/R14 validated path) =================
    float d[2][12][4];
#pragma unroll
    for (int mt = 0; mt < 2; ++mt)
#pragma unroll
        for (int nt = 0; nt < 12; ++nt)
#pragma unroll
            for (int x = 0; x < 4; ++x) d[mt][nt][x] = 0.f;

    for (int chunk = 0; chunk < 2; ++chunk) {
        __syncthreads();
        for (int i = tid; i < 64 * NK; i += 256) {
            int k = i % NK, c2 = i / NK;
            int c = chunk * 64 + c2;
            const float* base;
            int t;
            if (k < 128) { base = kv0 + (size_t)(k >> 6) * IMG; t = k & 63; }
            else { int kk = k - 128; base = kv1 + (size_t)(kk >> 6) * IMG; t = kk & 63; }
            int gy = wy8 + (t >> 3), gx = wx8 + (t & 7);
            float v = base[(size_t)c * HWSZ + gy * WW + gx];
            __nv_bfloat16 h, lo;
            bf16_split(v, h, lo);
            kbf[c2 * 392 + k] = h;
            kbf[25088 + c2 * 392 + k] = lo;
        }
        __syncthreads();

#pragma unroll
        for (int kc = 0; kc < 4; ++kc) {
            uint32_t ah[2][4], al[2][4];
#pragma unroll
            for (int mt = 0; mt < 2; ++mt) {
                uint32_t aa = sb + (warp_m * 32 + mt * 16 + (l & 15)) * 272 +
                              chunk * 128 + kc * 32 + (l >> 4) * 16;
                ldsm4(ah[mt], aa);
                ldsm4(al[mt], aa + 17408);
            }
#pragma unroll
            for (int n2 = 0; n2 < 6; ++n2) {
                uint32_t bh[4], bl[4];
                uint32_t ba = sb + 34816 + (kc * 16 + (l & 15)) * 784 +
                              (warp_n * 96 + n2 * 16) * 2 + (l >> 4) * 16;
                ldsm4t(bh, ba);
                ldsm4t(bl, ba + 50176);
#pragma unroll
                for (int mt = 0; mt < 2; ++mt) {
                    float* d0 = d[mt][n2 * 2];
                    float* d1 = d[mt][n2 * 2 + 1];
                    mma_bf16(d0, ah[mt], bh[0], bh[1]);
                    mma_bf16(d1, ah[mt], bh[2], bh[3]);
                    mma_bf16(d0, al[mt], bh[0], bh[1]);
                    mma_bf16(d1, al[mt], bh[2], bh[3]);
                    mma_bf16(d0, ah[mt], bl[0], bl[1]);
                    mma_bf16(d1, ah[mt], bl[2], bl[3]);
                }
            }
        }
    }

    // ---- store S frags -> smem fp32
    __syncthreads();
#pragma unroll
    for (int mt = 0; mt < 2; ++mt)
#pragma unroll
        for (int nt = 0; nt < 12; ++nt) {
            int r0 = warp_m * 32 + mt * 16 + (l >> 2);
            int c0 = warp_n * 96 + nt * 8 + (l & 3) * 2;
            *(float2*)(s_s + (size_t)r0 * SST + c0) =
                make_float2(d[mt][nt][0], d[mt][nt][1]);
            *(float2*)(s_s + (size_t)(r0 + 8) * SST + c0) =
                make_float2(d[mt][nt][2], d[mt][nt][3]);
        }
    __syncthreads();

    // ---- parallel softmax; write P bf16 hi/lo [q][k] row-major
    const float SCALE = 0.08838834764831845f;
    if (tid < 128) {
        int r = tid & 63, br = tid >> 6;
        float* row = s_s + (size_t)r * SST;
        float msk = s_m[r];
        int k0 = br ? 128 : 0, k1 = br ? 384 : 128;
        float m0 = -3.4e38f, m1 = -3.4e38f;
        for (int k = k0; k < k1; k += 2) {
            m0 = fmaxf(m0, row[k]);
            m1 = fmaxf(m1, row[k + 1]);
        }
        float m = fmaxf(m0, m1) * SCALE;
        float s0 = 0.f, s1 = 0.f;
        for (int k = k0; k < k1; k += 2) {
            float e0 = __expf(row[k] * SCALE - m);
            float e1 = __expf(row[k + 1] * SCALE - m);
            row[k] = e0; row[k + 1] = e1;
            s0 += e0; s1 += e1;
        }
        float wgt = br ? (1.f - msk) : msk;
        float inv = wgt / (s0 + s1);
        for (int k = k0; k < k1; ++k) {
            __nv_bfloat16 h, lo;
            bf16_split(row[k] * inv, h, lo);
            ph[(size_t)r * 392 + k] = h;
            pl[(size_t)r * 392 + k] = lo;
        }
    }

    // ================= PV via HMMA: O[64q x 128c] ==========================
    float od[2][4][4];
#pragma unroll
    for (int mt = 0; mt < 2; ++mt)
#pragma unroll
        for (int nt = 0; nt < 4; ++nt)
#pragma unroll
            for (int x = 0; x < 4; ++x) od[mt][nt][x] = 0.f;

    int n0 = warp_n * 32;  // warp's c base

    for (int chunk = 0; chunk < 3; ++chunk) {
        __syncthreads();
        // V chunk: [c rows 128][k cols 128] bf16 hi/lo, rows 272B
        for (int i = tid; i < 128 * 128; i += 256) {
            int kk = i & 127, c = i >> 7;
            int k = chunk * 128 + kk;
            const float* base;
            int t;
            if (k < 128) { base = kv0 + (size_t)(k >> 6) * IMG; t = k & 63; }
            else { int k2 = k - 128; base = kv1 + (size_t)(k2 >> 6) * IMG; t = k2 & 63; }
            int gy = wy8 + (t >> 3), gx = wx8 + (t & 7);
            float v = base[(size_t)c * HWSZ + gy * WW + gx];
            __nv_bfloat16 h, lo;
            bf16_split(v, h, lo);
            vbf[c * 136 + kk] = h;
            vbf[17408 + c * 136 + kk] = lo;
        }
        __syncthreads();

#pragma unroll
        for (int ks = 0; ks < 8; ++ks) {
            int kg = chunk * 8 + ks;
            uint32_t ah[2][4], al[2][4];
#pragma unroll
            for (int mt = 0; mt < 2; ++mt) {
                uint32_t pa = sb + 100352 +
                    (warp_m * 32 + mt * 16 + (l & 15)) * 784 +
                    kg * 32 + (l >> 4) * 16;
                ldsm4(ah[mt], pa);
                ldsm4(al[mt], pa + 50176);
            }
#pragma unroll
            for (int g = 0; g < 2; ++g) {
                uint32_t bh[4], bl[4];
                uint32_t ba = sb + (n0 + g * 16 + (l & 15)) * 272 +
                              ks * 32 + (l >> 4) * 16;
                ldsm4(bh, ba);
                ldsm4(bl, ba + 34816);
#pragma unroll
                for (int mt = 0; mt < 2; ++mt) {
                    float* d0 = od[mt][g * 2];
                    float* d1 = od[mt][g * 2 + 1];
                    // non-trans B pairing: (r0,r2) = n0-7, (r1,r3) = n8-15
                    mma_bf16(d0, ah[mt], bh[0], bh[2]);
                    mma_bf16(d1, ah[mt], bh[1], bh[3]);
                    mma_bf16(d0, al[mt], bh[0], bh[2]);
                    mma_bf16(d1, al[mt], bh[1], bh[3]);
                    mma_bf16(d0, ah[mt], bl[0], bl[2]);
                    mma_bf16(d1, ah[mt], bl[1], bl[3]);
                }
            }
        }
    }

    // ---- O frags -> smem [c][q], then residual RMW
    __syncthreads();
#pragma unroll
    for (int mt = 0; mt < 2; ++mt)
#pragma unroll
        for (int nt = 0; nt < 4; ++nt) {
            int q0 = warp_m * 32 + mt * 16 + (l >> 2);
            int c0 = n0 + (nt >> 1) * 16 + (nt & 1) * 8 + (l & 3) * 2;
            s_o[(size_t)c0 * OST + q0]           = od[mt][nt][0];
            s_o[(size_t)(c0 + 1) * OST + q0]     = od[mt][nt][1];
            s_o[(size_t)c0 * OST + q0 + 8]       = od[mt][nt][2];
            s_o[(size_t)(c0 + 1) * OST + q0 + 8] = od[mt][nt][3];
        }
    __syncthreads();
    for (int i = tid; i < 64 * CC; i += 256) {
        int q = i & 63, c = i >> 6;
        int gy = wy8 + (q >> 3), gx = wx8 + (q & 7);
        qimg[(size_t)c * HWSZ + gy * WW + gx] += s_o[(size_t)c * OST + q];
    }
}

// ---------------------------------------------------------------------------
extern "C" void kernel_launch(void* const* d_in, const int* in_sizes, int n_in,
                              void* d_out, int out_size)
{
    const float* xq   = (const float*)d_in[0];
    const float* xkvw = (const float*)d_in[1];
    const float* xkv  = (const float*)d_in[2];
    const float* em   = (const float*)d_in[3];
    const float* Wq   = (const float*)d_in[4];
    const float* bq   = (const float*)d_in[5];
    const float* aq   = (const float*)d_in[6];
    const float* Wkv  = (const float*)d_in[7];
    const float* bkv  = (const float*)d_in[8];
    const float* akv  = (const float*)d_in[9];
    const float* Wff  = (const float*)d_in[10];
    const float* bff  = (const float*)d_in[11];
    const float* aff  = (const float*)d_in[12];
    float* out = (float*)d_out;

    float *gQ = nullptr, *gKV = nullptr, *gKVw = nullptr;
    float *gV = nullptr, *gM = nullptr, *gU = nullptr;
    cudaGetSymbolAddress((void**)&gQ,   g_Q);
    cudaGetSymbolAddress((void**)&gKV,  g_KV);
    cudaGetSymbolAddress((void**)&gKVw, g_KVw);
    cudaGetSymbolAddress((void**)&gV,   g_V);
    cudaGetSymbolAddress((void**)&gM,   g_M);
    cudaGetSymbolAddress((void**)&gU,   g_U);

    __nv_bfloat16* gVh = (__nv_bfloat16*)gV;
    __nv_bfloat16* gUh = (__nv_bfloat16*)gU;

    cudaFuncSetAttribute(win_attn, cudaFuncAttributeMaxDynamicSharedMemorySize,
                         ATTN_SMEM);
    cudaFuncSetAttribute(wino_gemm_mma,
                         cudaFuncAttributeMaxDynamicSharedMemorySize, GEMM_SMEM);

    dim3 blk(256);

    wino_filt3<<<192, blk>>>(Wq, Wkv, Wff, gUh);

    wino_in14<<<dim3(32, 64, 14), blk>>>(xq, xkv, xkvw, gVh);
    wino_gemm_mma<<<dim3(64, 36, 14), blk, GEMM_SMEM>>>(gVh, gUh, gM, 1);
    wino_out14<<<dim3(16, 64, 14), blk>>>(gM, xq, xkv, xkvw, gQ, gKV, gKVw,
                                          bq, aq, bkv, akv, 1);

    win_attn<<<2048, blk, ATTN_SMEM>>>(gQ, gKV, gKVw, em);

    wino_in<<<dim3(32, 64, 2), blk>>>(gQ, gVh);
    wino_gemm_mma<<<dim3(64, 36, 2), blk, GEMM_SMEM>>>(gVh, gUh, gM, 0);
    wino_out14<<<dim3(16, 64, 2), blk>>>(gM, gQ, gQ, gQ, out, out, out,
                                         bff, aff, bff, aff, 0);
}

// round 16
// speedup vs baseline: 1.5092x; 1.0991x over previous
#include <cuda_runtime.h>
#include <cuda_bf16.h>
#include <cstdint>

#define HH 256
#define WW 256
#define CC 128
#define HWSZ 65536
#define IMG (CC * HH * WW)
#define VIMG (36ull * 128 * 4096)

// ---------------- scratch ----------------------------------------------------
__device__ float g_Q[2ull * IMG];
__device__ float g_KV[4ull * IMG];
__device__ float g_KVw[8ull * IMG];
__device__ float g_V[14ull * VIMG];
__device__ float g_M[14ull * VIMG];
__device__ float g_U[3ull * 36 * 128 * 128];

// ---------------- helpers ----------------------------------------------------
__device__ __forceinline__ void cp16(uint32_t saddr, const void* g) {
    asm volatile("cp.async.cg.shared.global [%0], [%1], 16;"
                 :: "r"(saddr), "l"(g) : "memory");
}
#define CP_COMMIT() asm volatile("cp.async.commit_group;" ::: "memory")
#define CP_WAIT(n)  asm volatile("cp.async.wait_group %0;" :: "n"(n) : "memory")

__device__ __forceinline__ uint32_t smem_u32(const void* p) {
    uint32_t a;
    asm("{ .reg .u64 t; cvta.to.shared.u64 t, %1; cvt.u32.u64 %0, t; }"
        : "=r"(a) : "l"(p));
    return a;
}
__device__ __forceinline__ void ldsm4(uint32_t* r, uint32_t a) {
    asm volatile("ldmatrix.sync.aligned.m8n8.x4.shared.b16 {%0,%1,%2,%3}, [%4];"
        : "=r"(r[0]), "=r"(r[1]), "=r"(r[2]), "=r"(r[3]) : "r"(a));
}
__device__ __forceinline__ void ldsm4t(uint32_t* r, uint32_t a) {
    asm volatile("ldmatrix.sync.aligned.m8n8.x4.trans.shared.b16 {%0,%1,%2,%3}, [%4];"
        : "=r"(r[0]), "=r"(r[1]), "=r"(r[2]), "=r"(r[3]) : "r"(a));
}
__device__ __forceinline__ void mma_bf16(float* d, const uint32_t* a,
                                         uint32_t b0, uint32_t b1) {
    asm volatile(
        "mma.sync.aligned.m16n8k16.row.col.f32.bf16.bf16.f32 "
        "{%0,%1,%2,%3}, {%4,%5,%6,%7}, {%8,%9}, {%0,%1,%2,%3};"
        : "+f"(d[0]), "+f"(d[1]), "+f"(d[2]), "+f"(d[3])
        : "r"(a[0]), "r"(a[1]), "r"(a[2]), "r"(a[3]), "r"(b0), "r"(b1));
}

#define BTCOMB(d0,d1,d2,d3,d4,d5,o0,o1,o2,o3,o4,o5) do {                   \
    o0 = 4.f*(d0) - 5.f*(d2) + (d4);                                       \
    float _a = (d4) - 4.f*(d2), _b = (d3) - 4.f*(d1);                      \
    o1 = _a + _b; o2 = _a - _b;                                            \
    float _c = (d4) - (d2), _e = 2.f*((d3) - (d1));                        \
    o3 = _c + _e; o4 = _c - _e;                                            \
    o5 = 4.f*(d1) - 5.f*(d3) + (d5);                                       \
} while (0)

#define ATCOMB(m0,m1,m2,m3,m4,m5,o0,o1,o2,o3) do {                         \
    float _s = (m1)+(m2), _d = (m1)-(m2), _t = (m3)+(m4), _u = (m3)-(m4);  \
    o0 = (m0) + _s + _t;                                                   \
    o1 = _d + 2.f*_u;                                                      \
    o2 = _s + 4.f*_t;                                                      \
    o3 = _d + 8.f*_u + (m5);                                               \
} while (0)

#define GCOMB(w0,w1,w2,o0,o1,o2,o3,o4,o5) do {                             \
    o0 = 0.25f*(w0);                                                       \
    float _n = -(w0) - (w2);                                               \
    o1 = (_n - (w1)) * (1.f/6.f);                                          \
    o2 = (_n + (w1)) * (1.f/6.f);                                          \
    float _p = (w0)*(1.f/24.f) + (w2)*(1.f/6.f), _q = (w1)*(1.f/12.f);     \
    o3 = _p + _q; o4 = _p - _q;                                            \
    o5 = (w2);                                                             \
} while (0)

__device__ __forceinline__ void bf16_split(float v, __nv_bfloat16& h,
                                           __nv_bfloat16& l) {
    h = __float2bfloat16(v);
    l = __float2bfloat16(v - __bfloat162float(h));
}

// ---------------------------------------------------------------------------
// Filter transform -> bf16 hi/lo planes, layout [set][pos][oc][ic]
// ---------------------------------------------------------------------------
__global__ __launch_bounds__(256) void wino_filt3(
    const float* __restrict__ W0, const float* __restrict__ W1,
    const float* __restrict__ W2, __nv_bfloat16* __restrict__ Uh)
{
    __nv_bfloat16* Ul = Uh + 3ull * 36 * 16384;
    int idx = blockIdx.x * 256 + threadIdx.x;
    if (idx >= 3 * 16384) return;
    int set = idx >> 14, e = idx & 16383;
    int oc = e & 127, ic = e >> 7;
    const float* W = (set == 0) ? W0 : (set == 1) ? W1 : W2;
    size_t soff = (size_t)set * (36 * 16384);
    float w[3][3];
#pragma unroll
    for (int a = 0; a < 3; ++a)
#pragma unroll
        for (int b = 0; b < 3; ++b)
            w[a][b] = W[(size_t)oc * 1152 + ic * 9 + a * 3 + b];
    float ee[6][3];
#pragma unroll
    for (int b = 0; b < 3; ++b)
        GCOMB(w[0][b], w[1][b], w[2][b],
              ee[0][b], ee[1][b], ee[2][b], ee[3][b], ee[4][b], ee[5][b]);
#pragma unroll
    for (int i = 0; i < 6; ++i) {
        float u[6];
        GCOMB(ee[i][0], ee[i][1], ee[i][2], u[0], u[1], u[2], u[3], u[4], u[5]);
#pragma unroll
        for (int j = 0; j < 6; ++j) {
            size_t off = soff + (size_t)(i * 6 + j) * 16384 + oc * 128 + ic;
            __nv_bfloat16 h, l;
            bf16_split(u[j], h, l);
            Uh[off] = h; Ul[off] = l;
        }
    }
}

// ---------------------------------------------------------------------------
// Merged input transform -> bf16 hi/lo V planes [img][pos][ic][tile]
// ---------------------------------------------------------------------------
__global__ __launch_bounds__(256) void wino_in14(
    const float* __restrict__ xq, const float* __restrict__ xkv,
    const float* __restrict__ xkvw, __nv_bfloat16* __restrict__ vh)
{
    __nv_bfloat16* vl = vh + 14ull * VIMG;
    __shared__ __align__(16) float s_d[4][6][264];
    int img = blockIdx.z, ty = blockIdx.y, c4 = blockIdx.x;
    int tid = threadIdx.x;
    const float* xb;
    if (img < 2)      xb = xq   + (size_t)img * IMG;
    else if (img < 6) xb = xkv  + (size_t)(img - 2) * IMG;
    else              xb = xkvw + (size_t)(img - 6) * IMG;
    xb += (size_t)(c4 * 4) * HWSZ;

    for (int i = tid; i < 4 * 6 * 258; i += 256) {
        int c = i / (6 * 258);
        int rem = i - c * (6 * 258);
        int r = rem / 258, col = rem - r * 258;
        int gy = ty * 4 - 1 + r, gx = col - 1;
        float v = 0.f;
        if ((unsigned)gy < 256u && (unsigned)gx < 256u)
            v = xb[(size_t)c * HWSZ + gy * 256 + gx];
        s_d[c][r][col] = v;
    }
    __syncthreads();

    int tx = tid & 63, c = tid >> 6;
    float d[6][6];
#pragma unroll
    for (int r = 0; r < 6; ++r) {
        const float4* row = (const float4*)s_d[c][r];
        float4 a = row[tx], b = row[tx + 1];
        d[r][0] = a.x; d[r][1] = a.y; d[r][2] = a.z;
        d[r][3] = a.w; d[r][4] = b.x; d[r][5] = b.y;
    }
    float e[6][6];
#pragma unroll
    for (int j = 0; j < 6; ++j)
        BTCOMB(d[0][j], d[1][j], d[2][j], d[3][j], d[4][j], d[5][j],
               e[0][j], e[1][j], e[2][j], e[3][j], e[4][j], e[5][j]);

    size_t base = (size_t)img * VIMG + (size_t)(c4 * 4 + c) * 4096 +
                  ty * 64 + tx;
#pragma unroll
    for (int i = 0; i < 6; ++i) {
        float o[6];
        BTCOMB(e[i][0], e[i][1], e[i][2], e[i][3], e[i][4], e[i][5],
               o[0], o[1], o[2], o[3], o[4], o[5]);
#pragma unroll
        for (int j = 0; j < 6; ++j) {
            size_t off = base + (size_t)(i * 6 + j) * 524288;
            __nv_bfloat16 h, l;
            bf16_split(o[j], h, l);
            vh[off] = h; vl[off] = l;
        }
    }
}

// FF-stage input transform (2 images from gQ)
__global__ __launch_bounds__(256) void wino_in(
    const float* __restrict__ x, __nv_bfloat16* __restrict__ vh)
{
    __nv_bfloat16* vl = vh + 14ull * VIMG;
    __shared__ __align__(16) float s_d[4][6][264];
    int img = blockIdx.z, ty = blockIdx.y, c4 = blockIdx.x;
    int tid = threadIdx.x;
    const float* xb = x + (size_t)img * IMG + (size_t)(c4 * 4) * HWSZ;

    for (int i = tid; i < 4 * 6 * 258; i += 256) {
        int c = i / (6 * 258);
        int rem = i - c * (6 * 258);
        int r = rem / 258, col = rem - r * 258;
        int gy = ty * 4 - 1 + r, gx = col - 1;
        float v = 0.f;
        if ((unsigned)gy < 256u && (unsigned)gx < 256u)
            v = xb[(size_t)c * HWSZ + gy * 256 + gx];
        s_d[c][r][col] = v;
    }
    __syncthreads();

    int tx = tid & 63, c = tid >> 6;
    float d[6][6];
#pragma unroll
    for (int r = 0; r < 6; ++r) {
        const float4* row = (const float4*)s_d[c][r];
        float4 a = row[tx], b = row[tx + 1];
        d[r][0] = a.x; d[r][1] = a.y; d[r][2] = a.z;
        d[r][3] = a.w; d[r][4] = b.x; d[r][5] = b.y;
    }
    float e[6][6];
#pragma unroll
    for (int j = 0; j < 6; ++j)
        BTCOMB(d[0][j], d[1][j], d[2][j], d[3][j], d[4][j], d[5][j],
               e[0][j], e[1][j], e[2][j], e[3][j], e[4][j], e[5][j]);

    size_t base = (size_t)img * VIMG + (size_t)(c4 * 4 + c) * 4096 +
                  ty * 64 + tx;
#pragma unroll
    for (int i = 0; i < 6; ++i) {
        float o[6];
        BTCOMB(e[i][0], e[i][1], e[i][2], e[i][3], e[i][4], e[i][5],
               o[0], o[1], o[2], o[3], o[4], o[5]);
#pragma unroll
        for (int j = 0; j < 6; ++j) {
            size_t off = base + (size_t)(i * 6 + j) * 524288;
            __nv_bfloat16 h, l;
            bf16_split(o[j], h, l);
            vh[off] = h; vl[off] = l;
        }
    }
}

// ---------------------------------------------------------------------------
// Winograd GEMM v4 (HMMA, R14/R15 passing version)
// ---------------------------------------------------------------------------
#define GEMM_SMEM 59392
#define AS_STAGE 20480
#define AS_TERM  10240
#define BS_BASE  40960
#define BS_STAGE 9216
#define BS_TERM  4608

__global__ __launch_bounds__(256, 2) void wino_gemm_mma(
    const __nv_bfloat16* __restrict__ vh, const __nv_bfloat16* __restrict__ uh,
    float* __restrict__ mout, int route)
{
    extern __shared__ __align__(16) char smx[];
    const __nv_bfloat16* vl = vh + 14ull * VIMG;
    const __nv_bfloat16* ul = uh + 3ull * 36 * 16384;

    int pos = blockIdx.y, img = blockIdx.z, tb = blockIdx.x;
    int tid = threadIdx.x, l = tid & 31, wid = tid >> 5;
    int warp_m = wid & 1, warp_n = wid >> 1;

    int uset = route ? ((img < 2) ? 0 : 1) : 2;
    size_t uoff = (size_t)uset * (36 * 16384) + (size_t)pos * 16384;
    size_t voff = (size_t)img * VIMG + (size_t)pos * 524288 + tb * 64;

    uint32_t sb = smem_u32(smx);

#define COPY_CHUNK(chunk, buf) do {                                         \
    int _ic0 = (chunk) * 32;                                                \
    _Pragma("unroll")                                                       \
    for (int _i = 0; _i < 4; ++_i) {                                        \
        int _t = tid + _i * 256;                                            \
        int _term = _t >> 9, _r = (_t >> 2) & 127, _s = _t & 3;             \
        const __nv_bfloat16* _src =                                         \
            (_term ? ul : uh) + uoff + _r * 128 + _ic0 + _s * 8;            \
        cp16(sb + (buf) * AS_STAGE + _term * AS_TERM + _r * 80 + _s * 16,   \
             _src);                                                         \
    }                                                                       \
    _Pragma("unroll")                                                       \
    for (int _i = 0; _i < 2; ++_i) {                                        \
        int _j = tid + _i * 256;                                            \
        int _bt = _j >> 8, _br = (_j >> 3) & 31, _bs = _j & 7;              \
        const __nv_bfloat16* _bsrc =                                        \
            (_bt ? vl : vh) + voff + (size_t)(_ic0 + _br) * 4096 + _bs * 8; \
        cp16(sb + BS_BASE + (buf) * BS_STAGE + _bt * BS_TERM +              \
             _br * 144 + _bs * 16, _bsrc);                                  \
    }                                                                       \
    CP_COMMIT();                                                            \
} while (0)

    float d[4][2][4];
#pragma unroll
    for (int mt = 0; mt < 4; ++mt)
#pragma unroll
        for (int nt = 0; nt < 2; ++nt)
#pragma unroll
            for (int k = 0; k < 4; ++k) d[mt][nt][k] = 0.f;

    COPY_CHUNK(0, 0);

    for (int c = 0; c < 4; ++c) {
        int buf = c & 1;
        if (c < 3) {
            COPY_CHUNK(c + 1, buf ^ 1);
            CP_WAIT(1);
        } else {
            CP_WAIT(0);
        }
        __syncthreads();

#pragma unroll
        for (int ks = 0; ks < 2; ++ks) {
            uint32_t ah[4][4], al[4][4];
#pragma unroll
            for (int mt = 0; mt < 4; ++mt) {
                uint32_t aa = sb + buf * AS_STAGE +
                    (warp_m * 64 + mt * 16 + (l & 15)) * 80 +
                    ks * 32 + (l >> 4) * 16;
                ldsm4(ah[mt], aa);
                ldsm4(al[mt], aa + AS_TERM);
            }
            uint32_t bh[4], bl[4];
            uint32_t ba = sb + BS_BASE + buf * BS_STAGE +
                          (ks * 16 + (l & 15)) * 144 +
                          warp_n * 32 + (l >> 4) * 16;
            ldsm4t(bh, ba);
            ldsm4t(bl, ba + BS_TERM);
#pragma unroll
            for (int mt = 0; mt < 4; ++mt) {
                float* d0 = d[mt][0];
                float* d1 = d[mt][1];
                mma_bf16(d0, ah[mt], bh[0], bh[1]);
                mma_bf16(d1, ah[mt], bh[2], bh[3]);
                mma_bf16(d0, al[mt], bh[0], bh[1]);
                mma_bf16(d1, al[mt], bh[2], bh[3]);
                mma_bf16(d0, ah[mt], bl[0], bl[1]);
                mma_bf16(d1, ah[mt], bl[2], bl[3]);
            }
        }
        __syncthreads();
    }

    float* Mo = mout + (size_t)img * VIMG + (size_t)pos * 524288 + tb * 64;
#pragma unroll
    for (int mt = 0; mt < 4; ++mt)
#pragma unroll
        for (int nt = 0; nt < 2; ++nt) {
            int oc0 = warp_m * 64 + mt * 16 + (l >> 2);
            int t0  = warp_n * 16 + nt * 8 + (l & 3) * 2;
            float2 v01 = make_float2(d[mt][nt][0], d[mt][nt][1]);
            float2 v23 = make_float2(d[mt][nt][2], d[mt][nt][3]);
            *(float2*)(Mo + (size_t)oc0 * 4096 + t0) = v01;
            *(float2*)(Mo + (size_t)(oc0 + 8) * 4096 + t0) = v23;
        }
#undef COPY_CHUNK
}

// ---------------------------------------------------------------------------
// Merged output transform + bias + PReLU + residual, per-image routing.
// ---------------------------------------------------------------------------
__global__ __launch_bounds__(256) void wino_out14(
    const float* __restrict__ mout,
    const float* __restrict__ r0, const float* __restrict__ r1,
    const float* __restrict__ r2,
    float* __restrict__ y0, float* __restrict__ y1, float* __restrict__ y2,
    const float* __restrict__ bias0, const float* __restrict__ alpha0,
    const float* __restrict__ bias1, const float* __restrict__ alpha1,
    int route)
{
    __shared__ __align__(16) float s_o[8][4][256];
    int img = blockIdx.z, ty = blockIdx.y, og = blockIdx.x;
    int tid = threadIdx.x;

    const float* resid; float* y; const float* bias; const float* alpha;
    if (!route || img < 2) {
        resid = r0 + (size_t)img * IMG; y = y0 + (size_t)img * IMG;
        bias = bias0; alpha = alpha0;
    } else if (img < 6) {
        resid = r1 + (size_t)(img - 2) * IMG; y = y1 + (size_t)(img - 2) * IMG;
        bias = bias1; alpha = alpha1;
    } else {
        resid = r2 + (size_t)(img - 6) * IMG; y = y2 + (size_t)(img - 6) * IMG;
        bias = bias1; alpha = alpha1;
    }

#pragma unroll
    for (int it = 0; it < 2; ++it) {
        int item = tid + it * 256;
        int tx = item & 63, ol = item >> 6;
        const float* Mp = mout + (size_t)img * VIMG +
                          (size_t)(og * 8 + ol) * 4096 + ty * 64 + tx;
        float m[6][6];
#pragma unroll
        for (int pos = 0; pos < 36; ++pos)
            m[pos / 6][pos % 6] = Mp[(size_t)pos * 524288];
        float e[4][6];
#pragma unroll
        for (int j = 0; j < 6; ++j)
            ATCOMB(m[0][j], m[1][j], m[2][j], m[3][j], m[4][j], m[5][j],
                   e[0][j], e[1][j], e[2][j], e[3][j]);
#pragma unroll
        for (int r = 0; r < 4; ++r) {
            float o0, o1, o2, o3;
            ATCOMB(e[r][0], e[r][1], e[r][2], e[r][3], e[r][4], e[r][5],
                   o0, o1, o2, o3);
            ((float4*)s_o[ol][r])[tx] = make_float4(o0, o1, o2, o3);
        }
    }
    __syncthreads();

    float a = alpha[0];
    for (int i = tid; i < 8192; i += 256) {
        int ol = i >> 10, rem = i & 1023, r = rem >> 8, px = rem & 255;
        int oc = og * 8 + ol;
        int gy = ty * 4 + r;
        size_t addr = (size_t)oc * HWSZ + gy * 256 + px;
        float v = s_o[ol][r][px] + bias[oc];
        v = (v >= 0.f) ? v : a * v;
        y[addr] = resid[addr] + v;
    }
}

// ---------------------------------------------------------------------------
// Windowed dual-branch attention v7: same as R15 (QK+PV HMMA) but with
// restructured fill loops (shift-only indexing, per-chunk hoisted pointers,
// deep-unrolled c loops for MLP).
// ---------------------------------------------------------------------------
#define SST 392
#define OST 66
#define ATTN_SMEM 200960
#define NK 384

__global__ __launch_bounds__(256, 1) void win_attn(
    float* __restrict__ Qbuf, const float* __restrict__ KV,
    const float* __restrict__ KVw, const float* __restrict__ em)
{
    extern __shared__ __align__(16) float sm[];
    __nv_bfloat16* qbf = (__nv_bfloat16*)sm;
    __nv_bfloat16* kbf = (__nv_bfloat16*)sm + 17408;
    float* s_s = sm;
    __nv_bfloat16* ph = (__nv_bfloat16*)((char*)sm + 100352);
    __nv_bfloat16* pl = ph + 25088;
    __nv_bfloat16* vbf = (__nv_bfloat16*)sm;
    float* s_m = (float*)((char*)sm + 200704);
    float* s_o = sm;

    int bwin = blockIdx.x;
    int bb  = bwin >> 10;
    int wy8 = ((bwin >> 5) & 31) << 3;
    int wx8 = (bwin & 31) << 3;
    int tid = threadIdx.x;
    int l = tid & 31, wid = tid >> 5;
    int warp_m = wid & 1, warp_n = wid >> 1;
    uint32_t sb = smem_u32(sm);

    float* qimg = Qbuf + (size_t)bb * IMG;
    const float* kv0 = KV + (size_t)bb * 2 * IMG;
    const float* kv1 = KVw + (size_t)bb * 4 * IMG;

    // per-thread K/V gmem source for k slot (tid & 127), hoisted
    int kslot = tid & 127;          // within 128-k group
    int cpar = tid >> 7;            // c parity (0/1)
    int tw = kslot & 63;
    int kgy = wy8 + (tw >> 3), kgx = wx8 + (tw & 7);

    // ---- load Q as bf16 hi/lo [q][c] (272B rows)
    for (int i = tid; i < 64 * CC; i += 256) {
        int q = i & 63, c = i >> 6;
        int gy = wy8 + (q >> 3), gx = wx8 + (q & 7);
        float v = qimg[(size_t)c * HWSZ + gy * WW + gx];
        __nv_bfloat16 h, lo;
        bf16_split(v, h, lo);
        qbf[q * 136 + c] = h;
        qbf[8704 + q * 136 + c] = lo;
    }
    if (tid < 64) {
        int gy = wy8 + (tid >> 3), gx = wx8 + (tid & 7);
        s_m[tid] = em[(size_t)bb * HWSZ + gy * WW + gx];
    }

    // ================= QK via HMMA (3-term), 2 chunks of 64 channels ========
    float d[2][12][4];
#pragma unroll
    for (int mt = 0; mt < 2; ++mt)
#pragma unroll
        for (int nt = 0; nt < 12; ++nt)
#pragma unroll
            for (int x = 0; x < 4; ++x) d[mt][nt][x] = 0.f;

    for (int chunk = 0; chunk < 2; ++chunk) {
        __syncthreads();
        // K chunk fill: thread owns k = kb*128 + kslot; iterates over c.
#pragma unroll
        for (int kb = 0; kb < 3; ++kb) {
            int k = kb * 128 + kslot;
            const float* src;
            if (k < 128) src = kv0 + (size_t)(k >> 6) * IMG;
            else         src = kv1 + (size_t)((k - 128) >> 6) * IMG;
            src += kgy * WW + kgx;
            __nv_bfloat16* dh = kbf + k;
            __nv_bfloat16* dl = kbf + 25088 + k;
#pragma unroll 8
            for (int cb = 0; cb < 32; ++cb) {
                int c2 = cb * 2 + cpar;
                float v = src[(size_t)(chunk * 64 + c2) * HWSZ];
                __nv_bfloat16 h, lo;
                bf16_split(v, h, lo);
                dh[c2 * 392] = h;
                dl[c2 * 392] = lo;
            }
        }
        __syncthreads();

#pragma unroll
        for (int kc = 0; kc < 4; ++kc) {
            uint32_t ah[2][4], al[2][4];
#pragma unroll
            for (int mt = 0; mt < 2; ++mt) {
                uint32_t aa = sb + (warp_m * 32 + mt * 16 + (l & 15)) * 272 +
                              chunk * 128 + kc * 32 + (l >> 4) * 16;
                ldsm4(ah[mt], aa);
                ldsm4(al[mt], aa + 17408);
            }
#pragma unroll
            for (int n2 = 0; n2 < 6; ++n2) {
                uint32_t bh[4], bl[4];
                uint32_t ba = sb + 34816 + (kc * 16 + (l & 15)) * 784 +
                              (warp_n * 96 + n2 * 16) * 2 + (l >> 4) * 16;
                ldsm4t(bh, ba);
                ldsm4t(bl, ba + 50176);
#pragma unroll
                for (int mt = 0; mt < 2; ++mt) {
                    float* d0 = d[mt][n2 * 2];
                    float* d1 = d[mt][n2 * 2 + 1];
                    mma_bf16(d0, ah[mt], bh[0], bh[1]);
                    mma_bf16(d1, ah[mt], bh[2], bh[3]);
                    mma_bf16(d0, al[mt], bh[0], bh[1]);
                    mma_bf16(d1, al[mt], bh[2], bh[3]);
                    mma_bf16(d0, ah[mt], bl[0], bl[1]);
                    mma_bf16(d1, ah[mt], bl[2], bl[3]);
                }
            }
        }
    }

    // ---- store S frags -> smem fp32
    __syncthreads();
#pragma unroll
    for (int mt = 0; mt < 2; ++mt)
#pragma unroll
        for (int nt = 0; nt < 12; ++nt) {
            int r0 = warp_m * 32 + mt * 16 + (l >> 2);
            int c0 = warp_n * 96 + nt * 8 + (l & 3) * 2;
            *(float2*)(s_s + (size_t)r0 * SST + c0) =
                make_float2(d[mt][nt][0], d[mt][nt][1]);
            *(float2*)(s_s + (size_t)(r0 + 8) * SST + c0) =
                make_float2(d[mt][nt][2], d[mt][nt][3]);
        }
    __syncthreads();

    // ---- parallel softmax; write P bf16 hi/lo [q][k] row-major
    const float SCALE = 0.08838834764831845f;
    if (tid < 128) {
        int r = tid & 63, br = tid >> 6;
        float* row = s_s + (size_t)r * SST;
        float msk = s_m[r];
        int k0 = br ? 128 : 0, k1 = br ? 384 : 128;
        float m0 = -3.4e38f, m1 = -3.4e38f;
        for (int k = k0; k < k1; k += 2) {
            m0 = fmaxf(m0, row[k]);
            m1 = fmaxf(m1, row[k + 1]);
        }
        float m = fmaxf(m0, m1) * SCALE;
        float s0 = 0.f, s1 = 0.f;
        for (int k = k0; k < k1; k += 2) {
            float e0 = __expf(row[k] * SCALE - m);
            float e1 = __expf(row[k + 1] * SCALE - m);
            row[k] = e0; row[k + 1] = e1;
            s0 += e0; s1 += e1;
        }
        float wgt = br ? (1.f - msk) : msk;
        float inv = wgt / (s0 + s1);
        for (int k = k0; k < k1; ++k) {
            __nv_bfloat16 h, lo;
            bf16_split(row[k] * inv, h, lo);
            ph[(size_t)r * 392 + k] = h;
            pl[(size_t)r * 392 + k] = lo;
        }
    }

    // ================= PV via HMMA: O[64q x 128c] ==========================
    float od[2][4][4];
#pragma unroll
    for (int mt = 0; mt < 2; ++mt)
#pragma unroll
        for (int nt = 0; nt < 4; ++nt)
#pragma unroll
            for (int x = 0; x < 4; ++x) od[mt][nt][x] = 0.f;

    int n0 = warp_n * 32;

    for (int chunk = 0; chunk < 3; ++chunk) {
        __syncthreads();
        // V chunk fill: thread owns kk = kslot (k = chunk*128+kslot), iterates c.
        {
            int k = chunk * 128 + kslot;
            const float* src;
            if (k < 128) src = kv0 + (size_t)(k >> 6) * IMG;
            else         src = kv1 + (size_t)((k - 128) >> 6) * IMG;
            src += kgy * WW + kgx;
            __nv_bfloat16* dh = vbf + kslot;
            __nv_bfloat16* dl = vbf + 17408 + kslot;
#pragma unroll 8
            for (int cb = 0; cb < 64; ++cb) {
                int c = cb * 2 + cpar;
                float v = src[(size_t)c * HWSZ];
                __nv_bfloat16 h, lo;
                bf16_split(v, h, lo);
                dh[c * 136] = h;
                dl[c * 136] = lo;
            }
        }
        __syncthreads();

#pragma unroll
        for (int ks = 0; ks < 8; ++ks) {
            int kg = chunk * 8 + ks;
            uint32_t ah[2][4], al[2][4];
#pragma unroll
            for (int mt = 0; mt < 2; ++mt) {
                uint32_t pa = sb + 100352 +
                    (warp_m * 32 + mt * 16 + (l & 15)) * 784 +
                    kg * 32 + (l >> 4) * 16;
                ldsm4(ah[mt], pa);
                ldsm4(al[mt], pa + 50176);
            }
#pragma unroll
            for (int g = 0; g < 2; ++g) {
                uint32_t bh[4], bl[4];
                uint32_t ba = sb + (n0 + g * 16 + (l & 15)) * 272 +
                              ks * 32 + (l >> 4) * 16;
                ldsm4(bh, ba);
                ldsm4(bl, ba + 34816);
#pragma unroll
                for (int mt = 0; mt < 2; ++mt) {
                    float* d0 = od[mt][g * 2];
                    float* d1 = od[mt][g * 2 + 1];
                    mma_bf16(d0, ah[mt], bh[0], bh[2]);
                    mma_bf16(d1, ah[mt], bh[1], bh[3]);
                    mma_bf16(d0, al[mt], bh[0], bh[2]);
                    mma_bf16(d1, al[mt], bh[1], bh[3]);
                    mma_bf16(d0, ah[mt], bl[0], bl[2]);
                    mma_bf16(d1, ah[mt], bl[1], bl[3]);
                }
            }
        }
    }

    // ---- O frags -> smem [c][q], then residual RMW
    __syncthreads();
#pragma unroll
    for (int mt = 0; mt < 2; ++mt)
#pragma unroll
        for (int nt = 0; nt < 4; ++nt) {
            int q0 = warp_m * 32 + mt * 16 + (l >> 2);
            int c0 = n0 + (nt >> 1) * 16 + (nt & 1) * 8 + (l & 3) * 2;
            s_o[(size_t)c0 * OST + q0]           = od[mt][nt][0];
            s_o[(size_t)(c0 + 1) * OST + q0]     = od[mt][nt][1];
            s_o[(size_t)c0 * OST + q0 + 8]       = od[mt][nt][2];
            s_o[(size_t)(c0 + 1) * OST + q0 + 8] = od[mt][nt][3];
        }
    __syncthreads();
    for (int i = tid; i < 64 * CC; i += 256) {
        int q = i & 63, c = i >> 6;
        int gy = wy8 + (q >> 3), gx = wx8 + (q & 7);
        qimg[(size_t)c * HWSZ + gy * WW + gx] += s_o[(size_t)c * OST + q];
    }
}

// ---------------------------------------------------------------------------
extern "C" void kernel_launch(void* const* d_in, const int* in_sizes, int n_in,
                              void* d_out, int out_size)
{
    const float* xq   = (const float*)d_in[0];
    const float* xkvw = (const float*)d_in[1];
    const float* xkv  = (const float*)d_in[2];
    const float* em   = (const float*)d_in[3];
    const float* Wq   = (const float*)d_in[4];
    const float* bq   = (const float*)d_in[5];
    const float* aq   = (const float*)d_in[6];
    const float* Wkv  = (const float*)d_in[7];
    const float* bkv  = (const float*)d_in[8];
    const float* akv  = (const float*)d_in[9];
    const float* Wff  = (const float*)d_in[10];
    const float* bff  = (const float*)d_in[11];
    const float* aff  = (const float*)d_in[12];
    float* out = (float*)d_out;

    float *gQ = nullptr, *gKV = nullptr, *gKVw = nullptr;
    float *gV = nullptr, *gM = nullptr, *gU = nullptr;
    cudaGetSymbolAddress((void**)&gQ,   g_Q);
    cudaGetSymbolAddress((void**)&gKV,  g_KV);
    cudaGetSymbolAddress((void**)&gKVw, g_KVw);
    cudaGetSymbolAddress((void**)&gV,   g_V);
    cudaGetSymbolAddress((void**)&gM,   g_M);
    cudaGetSymbolAddress((void**)&gU,   g_U);

    __nv_bfloat16* gVh = (__nv_bfloat16*)gV;
    __nv_bfloat16* gUh = (__nv_bfloat16*)gU;

    cudaFuncSetAttribute(win_attn, cudaFuncAttributeMaxDynamicSharedMemorySize,
                         ATTN_SMEM);
    cudaFuncSetAttribute(wino_gemm_mma,
                         cudaFuncAttributeMaxDynamicSharedMemorySize, GEMM_SMEM);

    dim3 blk(256);

    wino_filt3<<<192, blk>>>(Wq, Wkv, Wff, gUh);

    wino_in14<<<dim3(32, 64, 14), blk>>>(xq, xkv, xkvw, gVh);
    wino_gemm_mma<<<dim3(64, 36, 14), blk, GEMM_SMEM>>>(gVh, gUh, gM, 1);
    wino_out14<<<dim3(16, 64, 14), blk>>>(gM, xq, xkv, xkvw, gQ, gKV, gKVw,
                                          bq, aq, bkv, akv, 1);

    win_attn<<<2048, blk, ATTN_SMEM>>>(gQ, gKV, gKVw, em);

    wino_in<<<dim3(32, 64, 2), blk>>>(gQ, gVh);
    wino_gemm_mma<<<dim3(64, 36, 2), blk, GEMM_SMEM>>>(gVh, gUh, gM, 0);
    wino_out14<<<dim3(16, 64, 2), blk>>>(gM, gQ, gQ, gQ, out, out, out,
                                         bff, aff, bff, aff, 0);
}

// round 17
// speedup vs baseline: 1.6072x; 1.0649x over previous
#include <cuda_runtime.h>
#include <cuda_bf16.h>
#include <cstdint>

#define HH 256
#define WW 256
#define CC 128
#define HWSZ 65536
#define IMG (CC * HH * WW)
#define VIMG (36ull * 128 * 4096)

// ---------------- scratch ----------------------------------------------------
__device__ float g_Q[2ull * IMG];
__device__ float g_KV[4ull * IMG];
__device__ float g_KVw[8ull * IMG];
__device__ float g_V[14ull * VIMG];
__device__ float g_M[14ull * VIMG];
__device__ float g_U[3ull * 36 * 128 * 128];

// ---------------- helpers ----------------------------------------------------
__device__ __forceinline__ void cp16(uint32_t saddr, const void* g) {
    asm volatile("cp.async.cg.shared.global [%0], [%1], 16;"
                 :: "r"(saddr), "l"(g) : "memory");
}
#define CP_COMMIT() asm volatile("cp.async.commit_group;" ::: "memory")
#define CP_WAIT(n)  asm volatile("cp.async.wait_group %0;" :: "n"(n) : "memory")

__device__ __forceinline__ uint32_t smem_u32(const void* p) {
    uint32_t a;
    asm("{ .reg .u64 t; cvta.to.shared.u64 t, %1; cvt.u32.u64 %0, t; }"
        : "=r"(a) : "l"(p));
    return a;
}
__device__ __forceinline__ void ldsm4(uint32_t* r, uint32_t a) {
    asm volatile("ldmatrix.sync.aligned.m8n8.x4.shared.b16 {%0,%1,%2,%3}, [%4];"
        : "=r"(r[0]), "=r"(r[1]), "=r"(r[2]), "=r"(r[3]) : "r"(a));
}
__device__ __forceinline__ void ldsm4t(uint32_t* r, uint32_t a) {
    asm volatile("ldmatrix.sync.aligned.m8n8.x4.trans.shared.b16 {%0,%1,%2,%3}, [%4];"
        : "=r"(r[0]), "=r"(r[1]), "=r"(r[2]), "=r"(r[3]) : "r"(a));
}
__device__ __forceinline__ void mma_bf16(float* d, const uint32_t* a,
                                         uint32_t b0, uint32_t b1) {
    asm volatile(
        "mma.sync.aligned.m16n8k16.row.col.f32.bf16.bf16.f32 "
        "{%0,%1,%2,%3}, {%4,%5,%6,%7}, {%8,%9}, {%0,%1,%2,%3};"
        : "+f"(d[0]), "+f"(d[1]), "+f"(d[2]), "+f"(d[3])
        : "r"(a[0]), "r"(a[1]), "r"(a[2]), "r"(a[3]), "r"(b0), "r"(b1));
}

#define BTCOMB(d0,d1,d2,d3,d4,d5,o0,o1,o2,o3,o4,o5) do {                   \
    o0 = 4.f*(d0) - 5.f*(d2) + (d4);                                       \
    float _a = (d4) - 4.f*(d2), _b = (d3) - 4.f*(d1);                      \
    o1 = _a + _b; o2 = _a - _b;                                            \
    float _c = (d4) - (d2), _e = 2.f*((d3) - (d1));                        \
    o3 = _c + _e; o4 = _c - _e;                                            \
    o5 = 4.f*(d1) - 5.f*(d3) + (d5);                                       \
} while (0)

#define ATCOMB(m0,m1,m2,m3,m4,m5,o0,o1,o2,o3) do {                         \
    float _s = (m1)+(m2), _d = (m1)-(m2), _t = (m3)+(m4), _u = (m3)-(m4);  \
    o0 = (m0) + _s + _t;                                                   \
    o1 = _d + 2.f*_u;                                                      \
    o2 = _s + 4.f*_t;                                                      \
    o3 = _d + 8.f*_u + (m5);                                               \
} while (0)

#define GCOMB(w0,w1,w2,o0,o1,o2,o3,o4,o5) do {                             \
    o0 = 0.25f*(w0);                                                       \
    float _n = -(w0) - (w2);                                               \
    o1 = (_n - (w1)) * (1.f/6.f);                                          \
    o2 = (_n + (w1)) * (1.f/6.f);                                          \
    float _p = (w0)*(1.f/24.f) + (w2)*(1.f/6.f), _q = (w1)*(1.f/12.f);     \
    o3 = _p + _q; o4 = _p - _q;                                            \
    o5 = (w2);                                                             \
} while (0)

__device__ __forceinline__ void bf16_split(float v, __nv_bfloat16& h,
                                           __nv_bfloat16& l) {
    h = __float2bfloat16(v);
    l = __float2bfloat16(v - __bfloat162float(h));
}

// ---------------------------------------------------------------------------
// Filter transform -> bf16 hi/lo planes, layout [set][pos][oc][ic]
// ---------------------------------------------------------------------------
__global__ __launch_bounds__(256) void wino_filt3(
    const float* __restrict__ W0, const float* __restrict__ W1,
    const float* __restrict__ W2, __nv_bfloat16* __restrict__ Uh)
{
    __nv_bfloat16* Ul = Uh + 3ull * 36 * 16384;
    int idx = blockIdx.x * 256 + threadIdx.x;
    if (idx >= 3 * 16384) return;
    int set = idx >> 14, e = idx & 16383;
    int oc = e & 127, ic = e >> 7;
    const float* W = (set == 0) ? W0 : (set == 1) ? W1 : W2;
    size_t soff = (size_t)set * (36 * 16384);
    float w[3][3];
#pragma unroll
    for (int a = 0; a < 3; ++a)
#pragma unroll
        for (int b = 0; b < 3; ++b)
            w[a][b] = W[(size_t)oc * 1152 + ic * 9 + a * 3 + b];
    float ee[6][3];
#pragma unroll
    for (int b = 0; b < 3; ++b)
        GCOMB(w[0][b], w[1][b], w[2][b],
              ee[0][b], ee[1][b], ee[2][b], ee[3][b], ee[4][b], ee[5][b]);
#pragma unroll
    for (int i = 0; i < 6; ++i) {
        float u[6];
        GCOMB(ee[i][0], ee[i][1], ee[i][2], u[0], u[1], u[2], u[3], u[4], u[5]);
#pragma unroll
        for (int j = 0; j < 6; ++j) {
            size_t off = soff + (size_t)(i * 6 + j) * 16384 + oc * 128 + ic;
            __nv_bfloat16 h, l;
            bf16_split(u[j], h, l);
            Uh[off] = h; Ul[off] = l;
        }
    }
}

// ---------------------------------------------------------------------------
// Merged input transform -> bf16 hi/lo V planes [img][pos][ic][tile]
// ---------------------------------------------------------------------------
__global__ __launch_bounds__(256) void wino_in14(
    const float* __restrict__ xq, const float* __restrict__ xkv,
    const float* __restrict__ xkvw, __nv_bfloat16* __restrict__ vh)
{
    __nv_bfloat16* vl = vh + 14ull * VIMG;
    __shared__ __align__(16) float s_d[4][6][264];
    int img = blockIdx.z, ty = blockIdx.y, c4 = blockIdx.x;
    int tid = threadIdx.x;
    const float* xb;
    if (img < 2)      xb = xq   + (size_t)img * IMG;
    else if (img < 6) xb = xkv  + (size_t)(img - 2) * IMG;
    else              xb = xkvw + (size_t)(img - 6) * IMG;
    xb += (size_t)(c4 * 4) * HWSZ;

    for (int i = tid; i < 4 * 6 * 258; i += 256) {
        int c = i / (6 * 258);
        int rem = i - c * (6 * 258);
        int r = rem / 258, col = rem - r * 258;
        int gy = ty * 4 - 1 + r, gx = col - 1;
        float v = 0.f;
        if ((unsigned)gy < 256u && (unsigned)gx < 256u)
            v = xb[(size_t)c * HWSZ + gy * 256 + gx];
        s_d[c][r][col] = v;
    }
    __syncthreads();

    int tx = tid & 63, c = tid >> 6;
    float d[6][6];
#pragma unroll
    for (int r = 0; r < 6; ++r) {
        const float4* row = (const float4*)s_d[c][r];
        float4 a = row[tx], b = row[tx + 1];
        d[r][0] = a.x; d[r][1] = a.y; d[r][2] = a.z;
        d[r][3] = a.w; d[r][4] = b.x; d[r][5] = b.y;
    }
    float e[6][6];
#pragma unroll
    for (int j = 0; j < 6; ++j)
        BTCOMB(d[0][j], d[1][j], d[2][j], d[3][j], d[4][j], d[5][j],
               e[0][j], e[1][j], e[2][j], e[3][j], e[4][j], e[5][j]);

    size_t base = (size_t)img * VIMG + (size_t)(c4 * 4 + c) * 4096 +
                  ty * 64 + tx;
#pragma unroll
    for (int i = 0; i < 6; ++i) {
        float o[6];
        BTCOMB(e[i][0], e[i][1], e[i][2], e[i][3], e[i][4], e[i][5],
               o[0], o[1], o[2], o[3], o[4], o[5]);
#pragma unroll
        for (int j = 0; j < 6; ++j) {
            size_t off = base + (size_t)(i * 6 + j) * 524288;
            __nv_bfloat16 h, l;
            bf16_split(o[j], h, l);
            vh[off] = h; vl[off] = l;
        }
    }
}

// FF-stage input transform (2 images from gQ)
__global__ __launch_bounds__(256) void wino_in(
    const float* __restrict__ x, __nv_bfloat16* __restrict__ vh)
{
    __nv_bfloat16* vl = vh + 14ull * VIMG;
    __shared__ __align__(16) float s_d[4][6][264];
    int img = blockIdx.z, ty = blockIdx.y, c4 = blockIdx.x;
    int tid = threadIdx.x;
    const float* xb = x + (size_t)img * IMG + (size_t)(c4 * 4) * HWSZ;

    for (int i = tid; i < 4 * 6 * 258; i += 256) {
        int c = i / (6 * 258);
        int rem = i - c * (6 * 258);
        int r = rem / 258, col = rem - r * 258;
        int gy = ty * 4 - 1 + r, gx = col - 1;
        float v = 0.f;
        if ((unsigned)gy < 256u && (unsigned)gx < 256u)
            v = xb[(size_t)c * HWSZ + gy * 256 + gx];
        s_d[c][r][col] = v;
    }
    __syncthreads();

    int tx = tid & 63, c = tid >> 6;
    float d[6][6];
#pragma unroll
    for (int r = 0; r < 6; ++r) {
        const float4* row = (const float4*)s_d[c][r];
        float4 a = row[tx], b = row[tx + 1];
        d[r][0] = a.x; d[r][1] = a.y; d[r][2] = a.z;
        d[r][3] = a.w; d[r][4] = b.x; d[r][5] = b.y;
    }
    float e[6][6];
#pragma unroll
    for (int j = 0; j < 6; ++j)
        BTCOMB(d[0][j], d[1][j], d[2][j], d[3][j], d[4][j], d[5][j],
               e[0][j], e[1][j], e[2][j], e[3][j], e[4][j], e[5][j]);

    size_t base = (size_t)img * VIMG + (size_t)(c4 * 4 + c) * 4096 +
                  ty * 64 + tx;
#pragma unroll
    for (int i = 0; i < 6; ++i) {
        float o[6];
        BTCOMB(e[i][0], e[i][1], e[i][2], e[i][3], e[i][4], e[i][5],
               o[0], o[1], o[2], o[3], o[4], o[5]);
#pragma unroll
        for (int j = 0; j < 6; ++j) {
            size_t off = base + (size_t)(i * 6 + j) * 524288;
            __nv_bfloat16 h, l;
            bf16_split(o[j], h, l);
            vh[off] = h; vl[off] = l;
        }
    }
}

// ---------------------------------------------------------------------------
// Winograd GEMM v5 (HMMA): single-shot smem staging, K=128 whole.
// Block = 128 oc x 64 tiles, 256 threads, 2 CTAs/SM (104 KB smem).
// smem: A 2 term x 128 rows x 272B = 69632; B 2 term x 128 rows x 144B = 36864
// ---------------------------------------------------------------------------
#define GEMM_SMEM 106496
#define GA_TERM  34816
#define GB_BASE  69632
#define GB_TERM  18432

__global__ __launch_bounds__(256, 2) void wino_gemm_mma(
    const __nv_bfloat16* __restrict__ vh, const __nv_bfloat16* __restrict__ uh,
    float* __restrict__ mout, int route)
{
    extern __shared__ __align__(16) char smx[];
    const __nv_bfloat16* vl = vh + 14ull * VIMG;
    const __nv_bfloat16* ul = uh + 3ull * 36 * 16384;

    int pos = blockIdx.y, img = blockIdx.z, tb = blockIdx.x;
    int tid = threadIdx.x, l = tid & 31, wid = tid >> 5;
    int warp_m = wid & 1, warp_n = wid >> 1;

    int uset = route ? ((img < 2) ? 0 : 1) : 2;
    size_t uoff = (size_t)uset * (36 * 16384) + (size_t)pos * 16384;
    size_t voff = (size_t)img * VIMG + (size_t)pos * 524288 + tb * 64;

    uint32_t sb = smem_u32(smx);

    // ---- single-shot staging: A (4096 cp16) + B (2048 cp16)
#pragma unroll
    for (int i = 0; i < 16; ++i) {
        int t = tid + i * 256;
        int term = t >> 11, r = (t >> 4) & 127, s = t & 15;
        const __nv_bfloat16* src = (term ? ul : uh) + uoff + r * 128 + s * 8;
        cp16(sb + term * GA_TERM + r * 272 + s * 16, src);
    }
#pragma unroll
    for (int i = 0; i < 8; ++i) {
        int t = tid + i * 256;
        int bt = t >> 10, br = (t >> 3) & 127, bs = t & 7;
        const __nv_bfloat16* src = (bt ? vl : vh) + voff +
                                   (size_t)br * 4096 + bs * 8;
        cp16(sb + GB_BASE + bt * GB_TERM + br * 144 + bs * 16, src);
    }
    CP_COMMIT();

    float d[4][2][4];
#pragma unroll
    for (int mt = 0; mt < 4; ++mt)
#pragma unroll
        for (int nt = 0; nt < 2; ++nt)
#pragma unroll
            for (int k = 0; k < 4; ++k) d[mt][nt][k] = 0.f;

    CP_WAIT(0);
    __syncthreads();

#pragma unroll
    for (int ks = 0; ks < 8; ++ks) {
        uint32_t ah[4][4], al[4][4];
#pragma unroll
        for (int mt = 0; mt < 4; ++mt) {
            uint32_t aa = sb + (warp_m * 64 + mt * 16 + (l & 15)) * 272 +
                          ks * 32 + (l >> 4) * 16;
            ldsm4(ah[mt], aa);
            ldsm4(al[mt], aa + GA_TERM);
        }
        uint32_t bh[4], bl[4];
        uint32_t ba = sb + GB_BASE + (ks * 16 + (l & 15)) * 144 +
                      warp_n * 32 + (l >> 4) * 16;
        ldsm4t(bh, ba);
        ldsm4t(bl, ba + GB_TERM);
#pragma unroll
        for (int mt = 0; mt < 4; ++mt) {
            float* d0 = d[mt][0];
            float* d1 = d[mt][1];
            mma_bf16(d0, ah[mt], bh[0], bh[1]);
            mma_bf16(d1, ah[mt], bh[2], bh[3]);
            mma_bf16(d0, al[mt], bh[0], bh[1]);
            mma_bf16(d1, al[mt], bh[2], bh[3]);
            mma_bf16(d0, ah[mt], bl[0], bl[1]);
            mma_bf16(d1, ah[mt], bl[2], bl[3]);
        }
    }

    float* Mo = mout + (size_t)img * VIMG + (size_t)pos * 524288 + tb * 64;
#pragma unroll
    for (int mt = 0; mt < 4; ++mt)
#pragma unroll
        for (int nt = 0; nt < 2; ++nt) {
            int oc0 = warp_m * 64 + mt * 16 + (l >> 2);
            int t0  = warp_n * 16 + nt * 8 + (l & 3) * 2;
            float2 v01 = make_float2(d[mt][nt][0], d[mt][nt][1]);
            float2 v23 = make_float2(d[mt][nt][2], d[mt][nt][3]);
            *(float2*)(Mo + (size_t)oc0 * 4096 + t0) = v01;
            *(float2*)(Mo + (size_t)(oc0 + 8) * 4096 + t0) = v23;
        }
}

// ---------------------------------------------------------------------------
// Merged output transform + bias + PReLU + residual, per-image routing.
// ---------------------------------------------------------------------------
__global__ __launch_bounds__(256) void wino_out14(
    const float* __restrict__ mout,
    const float* __restrict__ r0, const float* __restrict__ r1,
    const float* __restrict__ r2,
    float* __restrict__ y0, float* __restrict__ y1, float* __restrict__ y2,
    const float* __restrict__ bias0, const float* __restrict__ alpha0,
    const float* __restrict__ bias1, const float* __restrict__ alpha1,
    int route)
{
    __shared__ __align__(16) float s_o[8][4][256];
    int img = blockIdx.z, ty = blockIdx.y, og = blockIdx.x;
    int tid = threadIdx.x;

    const float* resid; float* y; const float* bias; const float* alpha;
    if (!route || img < 2) {
        resid = r0 + (size_t)img * IMG; y = y0 + (size_t)img * IMG;
        bias = bias0; alpha = alpha0;
    } else if (img < 6) {
        resid = r1 + (size_t)(img - 2) * IMG; y = y1 + (size_t)(img - 2) * IMG;
        bias = bias1; alpha = alpha1;
    } else {
        resid = r2 + (size_t)(img - 6) * IMG; y = y2 + (size_t)(img - 6) * IMG;
        bias = bias1; alpha = alpha1;
    }

#pragma unroll
    for (int it = 0; it < 2; ++it) {
        int item = tid + it * 256;
        int tx = item & 63, ol = item >> 6;
        const float* Mp = mout + (size_t)img * VIMG +
                          (size_t)(og * 8 + ol) * 4096 + ty * 64 + tx;
        float m[6][6];
#pragma unroll
        for (int pos = 0; pos < 36; ++pos)
            m[pos / 6][pos % 6] = Mp[(size_t)pos * 524288];
        float e[4][6];
#pragma unroll
        for (int j = 0; j < 6; ++j)
            ATCOMB(m[0][j], m[1][j], m[2][j], m[3][j], m[4][j], m[5][j],
                   e[0][j], e[1][j], e[2][j], e[3][j]);
#pragma unroll
        for (int r = 0; r < 4; ++r) {
            float o0, o1, o2, o3;
            ATCOMB(e[r][0], e[r][1], e[r][2], e[r][3], e[r][4], e[r][5],
                   o0, o1, o2, o3);
            ((float4*)s_o[ol][r])[tx] = make_float4(o0, o1, o2, o3);
        }
    }
    __syncthreads();

    float a = alpha[0];
    for (int i = tid; i < 8192; i += 256) {
        int ol = i >> 10, rem = i & 1023, r = rem >> 8, px = rem & 255;
        int oc = og * 8 + ol;
        int gy = ty * 4 + r;
        size_t addr = (size_t)oc * HWSZ + gy * 256 + px;
        float v = s_o[ol][r][px] + bias[oc];
        v = (v >= 0.f) ? v : a * v;
        y[addr] = resid[addr] + v;
    }
}

// ---------------------------------------------------------------------------
// Windowed dual-branch attention v7 (R16 passing version)
// ---------------------------------------------------------------------------
#define SST 392
#define OST 66
#define ATTN_SMEM 200960
#define NK 384

__global__ __launch_bounds__(256, 1) void win_attn(
    float* __restrict__ Qbuf, const float* __restrict__ KV,
    const float* __restrict__ KVw, const float* __restrict__ em)
{
    extern __shared__ __align__(16) float sm[];
    __nv_bfloat16* qbf = (__nv_bfloat16*)sm;
    __nv_bfloat16* kbf = (__nv_bfloat16*)sm + 17408;
    float* s_s = sm;
    __nv_bfloat16* ph = (__nv_bfloat16*)((char*)sm + 100352);
    __nv_bfloat16* pl = ph + 25088;
    __nv_bfloat16* vbf = (__nv_bfloat16*)sm;
    float* s_m = (float*)((char*)sm + 200704);
    float* s_o = sm;

    int bwin = blockIdx.x;
    int bb  = bwin >> 10;
    int wy8 = ((bwin >> 5) & 31) << 3;
    int wx8 = (bwin & 31) << 3;
    int tid = threadIdx.x;
    int l = tid & 31, wid = tid >> 5;
    int warp_m = wid & 1, warp_n = wid >> 1;
    uint32_t sb = smem_u32(sm);

    float* qimg = Qbuf + (size_t)bb * IMG;
    const float* kv0 = KV + (size_t)bb * 2 * IMG;
    const float* kv1 = KVw + (size_t)bb * 4 * IMG;

    int kslot = tid & 127;
    int cpar = tid >> 7;
    int tw = kslot & 63;
    int kgy = wy8 + (tw >> 3), kgx = wx8 + (tw & 7);

    for (int i = tid; i < 64 * CC; i += 256) {
        int q = i & 63, c = i >> 6;
        int gy = wy8 + (q >> 3), gx = wx8 + (q & 7);
        float v = qimg[(size_t)c * HWSZ + gy * WW + gx];
        __nv_bfloat16 h, lo;
        bf16_split(v, h, lo);
        qbf[q * 136 + c] = h;
        qbf[8704 + q * 136 + c] = lo;
    }
    if (tid < 64) {
        int gy = wy8 + (tid >> 3), gx = wx8 + (tid & 7);
        s_m[tid] = em[(size_t)bb * HWSZ + gy * WW + gx];
    }

    float d[2][12][4];
#pragma unroll
    for (int mt = 0; mt < 2; ++mt)
#pragma unroll
        for (int nt = 0; nt < 12; ++nt)
#pragma unroll
            for (int x = 0; x < 4; ++x) d[mt][nt][x] = 0.f;

    for (int chunk = 0; chunk < 2; ++chunk) {
        __syncthreads();
#pragma unroll
        for (int kb = 0; kb < 3; ++kb) {
            int k = kb * 128 + kslot;
            const float* src;
            if (k < 128) src = kv0 + (size_t)(k >> 6) * IMG;
            else         src = kv1 + (size_t)((k - 128) >> 6) * IMG;
            src += kgy * WW + kgx;
            __nv_bfloat16* dh = kbf + k;
            __nv_bfloat16* dl = kbf + 25088 + k;
#pragma unroll 8
            for (int cb = 0; cb < 32; ++cb) {
                int c2 = cb * 2 + cpar;
                float v = src[(size_t)(chunk * 64 + c2) * HWSZ];
                __nv_bfloat16 h, lo;
                bf16_split(v, h, lo);
                dh[c2 * 392] = h;
                dl[c2 * 392] = lo;
            }
        }
        __syncthreads();

#pragma unroll
        for (int kc = 0; kc < 4; ++kc) {
            uint32_t ah[2][4], al[2][4];
#pragma unroll
            for (int mt = 0; mt < 2; ++mt) {
                uint32_t aa = sb + (warp_m * 32 + mt * 16 + (l & 15)) * 272 +
                              chunk * 128 + kc * 32 + (l >> 4) * 16;
                ldsm4(ah[mt], aa);
                ldsm4(al[mt], aa + 17408);
            }
#pragma unroll
            for (int n2 = 0; n2 < 6; ++n2) {
                uint32_t bh[4], bl[4];
                uint32_t ba = sb + 34816 + (kc * 16 + (l & 15)) * 784 +
                              (warp_n * 96 + n2 * 16) * 2 + (l >> 4) * 16;
                ldsm4t(bh, ba);
                ldsm4t(bl, ba + 50176);
#pragma unroll
                for (int mt = 0; mt < 2; ++mt) {
                    float* d0 = d[mt][n2 * 2];
                    float* d1 = d[mt][n2 * 2 + 1];
                    mma_bf16(d0, ah[mt], bh[0], bh[1]);
                    mma_bf16(d1, ah[mt], bh[2], bh[3]);
                    mma_bf16(d0, al[mt], bh[0], bh[1]);
                    mma_bf16(d1, al[mt], bh[2], bh[3]);
                    mma_bf16(d0, ah[mt], bl[0], bl[1]);
                    mma_bf16(d1, ah[mt], bl[2], bl[3]);
                }
            }
        }
    }

    __syncthreads();
#pragma unroll
    for (int mt = 0; mt < 2; ++mt)
#pragma unroll
        for (int nt = 0; nt < 12; ++nt) {
            int r0 = warp_m * 32 + mt * 16 + (l >> 2);
            int c0 = warp_n * 96 + nt * 8 + (l & 3) * 2;
            *(float2*)(s_s + (size_t)r0 * SST + c0) =
                make_float2(d[mt][nt][0], d[mt][nt][1]);
            *(float2*)(s_s + (size_t)(r0 + 8) * SST + c0) =
                make_float2(d[mt][nt][2], d[mt][nt][3]);
        }
    __syncthreads();

    const float SCALE = 0.08838834764831845f;
    if (tid < 128) {
        int r = tid & 63, br = tid >> 6;
        float* row = s_s + (size_t)r * SST;
        float msk = s_m[r];
        int k0 = br ? 128 : 0, k1 = br ? 384 : 128;
        float m0 = -3.4e38f, m1 = -3.4e38f;
        for (int k = k0; k < k1; k += 2) {
            m0 = fmaxf(m0, row[k]);
            m1 = fmaxf(m1, row[k + 1]);
        }
        float m = fmaxf(m0, m1) * SCALE;
        float s0 = 0.f, s1 = 0.f;
        for (int k = k0; k < k1; k += 2) {
            float e0 = __expf(row[k] * SCALE - m);
            float e1 = __expf(row[k + 1] * SCALE - m);
            row[k] = e0; row[k + 1] = e1;
            s0 += e0; s1 += e1;
        }
        float wgt = br ? (1.f - msk) : msk;
        float inv = wgt / (s0 + s1);
        for (int k = k0; k < k1; ++k) {
            __nv_bfloat16 h, lo;
            bf16_split(row[k] * inv, h, lo);
            ph[(size_t)r * 392 + k] = h;
            pl[(size_t)r * 392 + k] = lo;
        }
    }

    float od[2][4][4];
#pragma unroll
    for (int mt = 0; mt < 2; ++mt)
#pragma unroll
        for (int nt = 0; nt < 4; ++nt)
#pragma unroll
            for (int x = 0; x < 4; ++x) od[mt][nt][x] = 0.f;

    int n0 = warp_n * 32;

    for (int chunk = 0; chunk < 3; ++chunk) {
        __syncthreads();
        {
            int k = chunk * 128 + kslot;
            const float* src;
            if (k < 128) src = kv0 + (size_t)(k >> 6) * IMG;
            else         src = kv1 + (size_t)((k - 128) >> 6) * IMG;
            src += kgy * WW + kgx;
            __nv_bfloat16* dh = vbf + kslot;
            __nv_bfloat16* dl = vbf + 17408 + kslot;
#pragma unroll 8
            for (int cb = 0; cb < 64; ++cb) {
                int c = cb * 2 + cpar;
                float v = src[(size_t)c * HWSZ];
                __nv_bfloat16 h, lo;
                bf16_split(v, h, lo);
                dh[c * 136] = h;
                dl[c * 136] = lo;
            }
        }
        __syncthreads();

#pragma unroll
        for (int ks = 0; ks < 8; ++ks) {
            int kg = chunk * 8 + ks;
            uint32_t ah[2][4], al[2][4];
#pragma unroll
            for (int mt = 0; mt < 2; ++mt) {
                uint32_t pa = sb + 100352 +
                    (warp_m * 32 + mt * 16 + (l & 15)) * 784 +
                    kg * 32 + (l >> 4) * 16;
                ldsm4(ah[mt], pa);
                ldsm4(al[mt], pa + 50176);
            }
#pragma unroll
            for (int g = 0; g < 2; ++g) {
                uint32_t bh[4], bl[4];
                uint32_t ba = sb + (n0 + g * 16 + (l & 15)) * 272 +
                              ks * 32 + (l >> 4) * 16;
                ldsm4(bh, ba);
                ldsm4(bl, ba + 34816);
#pragma unroll
                for (int mt = 0; mt < 2; ++mt) {
                    float* d0 = od[mt][g * 2];
                    float* d1 = od[mt][g * 2 + 1];
                    mma_bf16(d0, ah[mt], bh[0], bh[2]);
                    mma_bf16(d1, ah[mt], bh[1], bh[3]);
                    mma_bf16(d0, al[mt], bh[0], bh[2]);
                    mma_bf16(d1, al[mt], bh[1], bh[3]);
                    mma_bf16(d0, ah[mt], bl[0], bl[2]);
                    mma_bf16(d1, ah[mt], bl[1], bl[3]);
                }
            }
        }
    }

    __syncthreads();
#pragma unroll
    for (int mt = 0; mt < 2; ++mt)
#pragma unroll
        for (int nt = 0; nt < 4; ++nt) {
            int q0 = warp_m * 32 + mt * 16 + (l >> 2);
            int c0 = n0 + (nt >> 1) * 16 + (nt & 1) * 8 + (l & 3) * 2;
            s_o[(size_t)c0 * OST + q0]           = od[mt][nt][0];
            s_o[(size_t)(c0 + 1) * OST + q0]     = od[mt][nt][1];
            s_o[(size_t)c0 * OST + q0 + 8]       = od[mt][nt][2];
            s_o[(size_t)(c0 + 1) * OST + q0 + 8] = od[mt][nt][3];
        }
    __syncthreads();
    for (int i = tid; i < 64 * CC; i += 256) {
        int q = i & 63, c = i >> 6;
        int gy = wy8 + (q >> 3), gx = wx8 + (q & 7);
        qimg[(size_t)c * HWSZ + gy * WW + gx] += s_o[(size_t)c * OST + q];
    }
}

// ---------------------------------------------------------------------------
extern "C" void kernel_launch(void* const* d_in, const int* in_sizes, int n_in,
                              void* d_out, int out_size)
{
    const float* xq   = (const float*)d_in[0];
    const float* xkvw = (const float*)d_in[1];
    const float* xkv  = (const float*)d_in[2];
    const float* em   = (const float*)d_in[3];
    const float* Wq   = (const float*)d_in[4];
    const float* bq   = (const float*)d_in[5];
    const float* aq   = (const float*)d_in[6];
    const float* Wkv  = (const float*)d_in[7];
    const float* bkv  = (const float*)d_in[8];
    const float* akv  = (const float*)d_in[9];
    const float* Wff  = (const float*)d_in[10];
    const float* bff  = (const float*)d_in[11];
    const float* aff  = (const float*)d_in[12];
    float* out = (float*)d_out;

    float *gQ = nullptr, *gKV = nullptr, *gKVw = nullptr;
    float *gV = nullptr, *gM = nullptr, *gU = nullptr;
    cudaGetSymbolAddress((void**)&gQ,   g_Q);
    cudaGetSymbolAddress((void**)&gKV,  g_KV);
    cudaGetSymbolAddress((void**)&gKVw, g_KVw);
    cudaGetSymbolAddress((void**)&gV,   g_V);
    cudaGetSymbolAddress((void**)&gM,   g_M);
    cudaGetSymbolAddress((void**)&gU,   g_U);

    __nv_bfloat16* gVh = (__nv_bfloat16*)gV;
    __nv_bfloat16* gUh = (__nv_bfloat16*)gU;

    cudaFuncSetAttribute(win_attn, cudaFuncAttributeMaxDynamicSharedMemorySize,
                         ATTN_SMEM);
    cudaFuncSetAttribute(wino_gemm_mma,
                         cudaFuncAttributeMaxDynamicSharedMemorySize, GEMM_SMEM);

    dim3 blk(256);

    wino_filt3<<<192, blk>>>(Wq, Wkv, Wff, gUh);

    wino_in14<<<dim3(32, 64, 14), blk>>>(xq, xkv, xkvw, gVh);
    wino_gemm_mma<<<dim3(64, 36, 14), blk, GEMM_SMEM>>>(gVh, gUh, gM, 1);
    wino_out14<<<dim3(16, 64, 14), blk>>>(gM, xq, xkv, xkvw, gQ, gKV, gKVw,
                                          bq, aq, bkv, akv, 1);

    win_attn<<<2048, blk, ATTN_SMEM>>>(gQ, gKV, gKVw, em);

    wino_in<<<dim3(32, 64, 2), blk>>>(gQ, gVh);
    wino_gemm_mma<<<dim3(64, 36, 2), blk, GEMM_SMEM>>>(gVh, gUh, gM, 0);
    wino_out14<<<dim3(16, 64, 2), blk>>>(gM, gQ, gQ, gQ, out, out, out,
                                         bff, aff, bff, aff, 0);
}